// round 5
// baseline (speedup 1.0000x reference)
#include <cuda_runtime.h>
#include <cuda_bf16.h>

#define N_NODES 50000
#define N_EDGES 800000
#define N_GRAPHS 1024
#define DIM 300
#define N_LAYERS 5
#define FEAT 256
#define EPS 1e-5f
#define NBLK_SCAN ((N_NODES + 255) / 256)   // 196

// ---------------- scratch (static device globals; no allocation) -------------
__device__ float g_h[N_NODES * DIM];     // embed output (layer-0 input)
__device__ float g_hw[N_NODES * DIM];    // h @ W[l]
__device__ float g_agg[N_NODES * DIM];   // pre-BN accumulation
__device__ float g_stats[N_LAYERS * 2 * DIM];
__device__ float g_coef[2 * DIM];        // current layer BN scale/shift
__device__ float g_hg[N_GRAPHS * DIM];
__device__ float g_hid[N_GRAPHS * FEAT];
// CSR build
__device__ int g_deg[N_NODES];
__device__ int g_incl[N_NODES];
__device__ int g_bsum[NBLK_SCAN];
__device__ int g_boff[NBLK_SCAN];
__device__ int g_cursor[N_NODES];
__device__ int g_start[N_NODES + 1];
__device__ int g_csr[N_EDGES];           // row | (attr<<16)
__device__ int g_gstart[N_GRAPHS + 1];

// ---------------- node embedding + zero deg/stats ----------------------------
__global__ void embed_kernel(const int* __restrict__ x,
                             const float* __restrict__ emb1,
                             const float* __restrict__ emb2) {
    int i = blockIdx.x * blockDim.x + threadIdx.x;
    if (i < N_LAYERS * 2 * DIM) g_stats[i] = 0.f;
    if (i < N_NODES) g_deg[i] = 0;
    if (i >= N_NODES * DIM) return;
    int n = i / DIM, d = i - n * DIM;
    int a = x[2 * n], c = x[2 * n + 1];
    g_h[i] = emb1[a * DIM + d] + emb2[c * DIM + d];
}

// ---------------- CSR build ---------------------------------------------------
__global__ void hist_kernel(const int* __restrict__ ei) {
    int e = blockIdx.x * blockDim.x + threadIdx.x;
    if (e >= N_EDGES) return;
    atomicAdd(&g_deg[ei[N_EDGES + e]], 1);
}

__global__ void scan1_kernel() {
    __shared__ int s[256];
    int tid = threadIdx.x;
    int i = blockIdx.x * 256 + tid;
    int v = (i < N_NODES) ? g_deg[i] : 0;
    s[tid] = v;
    __syncthreads();
#pragma unroll
    for (int off = 1; off < 256; off <<= 1) {
        int t = (tid >= off) ? s[tid - off] : 0;
        __syncthreads();
        s[tid] += t;
        __syncthreads();
    }
    if (i < N_NODES) g_incl[i] = s[tid];
    if (tid == 255) g_bsum[blockIdx.x] = s[255];
}

__global__ void scan2_kernel() {
    __shared__ int s[256];
    int tid = threadIdx.x;
    s[tid] = (tid < NBLK_SCAN) ? g_bsum[tid] : 0;
    __syncthreads();
#pragma unroll
    for (int off = 1; off < 256; off <<= 1) {
        int t = (tid >= off) ? s[tid - off] : 0;
        __syncthreads();
        s[tid] += t;
        __syncthreads();
    }
    if (tid < NBLK_SCAN) g_boff[tid] = s[tid] - g_bsum[tid];
}

__global__ void scan3_kernel() {
    int i = blockIdx.x * blockDim.x + threadIdx.x;
    if (i >= N_NODES) return;
    g_start[i + 1] = g_incl[i] + g_boff[i >> 8];
    g_cursor[i] = 0;
    if (i == 0) g_start[0] = 0;
}

__global__ void fill_kernel(const int* __restrict__ ei,
                            const int* __restrict__ ea) {
    int e = blockIdx.x * blockDim.x + threadIdx.x;
    if (e >= N_EDGES) return;
    int row = ei[e];
    int col = ei[N_EDGES + e];
    int attr = ea[2 * e] * 3 + ea[2 * e + 1];  // 0..8
    int pos = g_start[col] + atomicAdd(&g_cursor[col], 1);
    g_csr[pos] = row | (attr << 16);
}

// ---------------- 3xTF32 tensor-core GEMM with fused BN+ReLU on A ------------
__device__ __forceinline__ unsigned f2tf32(float x) {
    unsigned u;
    asm("cvt.rna.tf32.f32 %0, %1;" : "=r"(u) : "f"(x));
    return u;
}

#define MMA_TF32(cc, A0, A1, A2, A3, B0, B1)                                   \
    asm volatile(                                                              \
        "mma.sync.aligned.m16n8k8.row.col.f32.tf32.tf32.f32 "                  \
        "{%0,%1,%2,%3},{%4,%5,%6,%7},{%8,%9},{%0,%1,%2,%3};"                   \
        : "+f"(cc[0]), "+f"(cc[1]), "+f"(cc[2]), "+f"(cc[3])                   \
        : "r"(A0), "r"(A1), "r"(A2), "r"(A3), "r"(B0), "r"(B1));

#define NKT 19            // ceil(300/16)
#define A_STR 136         // uint2 stride
#define B_STR 72
#define A_TILE (16 * A_STR)   // per buffer, uint2
#define B_TILE (16 * B_STR)
#define SMEM_U2 (2 * A_TILE + 2 * B_TILE)
#define SMEM_BYTES (SMEM_U2 * 8)

__device__ __forceinline__ uint2 split_tf32(float x) {
    unsigned hi = f2tf32(x);
    return make_uint2(hi, f2tf32(x - __uint_as_float(hi)));
}

__global__ __launch_bounds__(256)
void gemm_layer_tc(const float* __restrict__ Wl,   // [DIM, DIM] row-major
                   const float* __restrict__ src,  // g_h (l=0) or g_agg
                   int apply_bn) {
    extern __shared__ uint2 sm[];
    uint2* As = sm;                       // [2][16][A_STR]
    uint2* Bs = sm + 2 * A_TILE;          // [2][16][B_STR]

    const int tid = threadIdx.x;
    const int lane = tid & 31;
    const int warp = tid >> 5;
    const int g = lane >> 2;
    const int tg = lane & 3;
    const int wm = warp >> 1;
    const int wn = warp & 1;
    const int m0 = blockIdx.y * 128;
    const int n0 = blockIdx.x * 64;

    float c[2][4][4];
#pragma unroll
    for (int im = 0; im < 2; im++)
#pragma unroll
        for (int in = 0; in < 4; in++)
#pragma unroll
            for (int j = 0; j < 4; j++) c[im][in][j] = 0.f;

    const int a_m = tid >> 1;          // 0..127
    const int a_k = (tid & 1) * 8;     // 0 or 8
    const int b_k = tid >> 4;          // 0..15
    const int b_n = (tid & 15) * 4;    // 0..60
    const int gm = m0 + a_m;

    float ar[8], br[4];

    // ---- A loader (with optional BN+ReLU) into ar[8] for k-tile kt ----
    auto loadA = [&](int kt) {
        int gk = kt * 16 + a_k;
        if (gm < N_NODES && gk + 7 < DIM) {
            const float4 v0 = *(const float4*)&src[gm * DIM + gk];
            const float4 v1 = *(const float4*)&src[gm * DIM + gk + 4];
            ar[0] = v0.x; ar[1] = v0.y; ar[2] = v0.z; ar[3] = v0.w;
            ar[4] = v1.x; ar[5] = v1.y; ar[6] = v1.z; ar[7] = v1.w;
        } else {
#pragma unroll
            for (int j = 0; j < 8; j++)
                ar[j] = (gm < N_NODES && gk + j < DIM) ? src[gm * DIM + gk + j]
                                                       : 0.f;
        }
        if (apply_bn) {
            if (gk + 7 < DIM) {
                const float4 s0 = *(const float4*)&g_coef[gk];
                const float4 s1 = *(const float4*)&g_coef[gk + 4];
                const float4 t0 = *(const float4*)&g_coef[DIM + gk];
                const float4 t1 = *(const float4*)&g_coef[DIM + gk + 4];
                ar[0] = fmaxf(ar[0] * s0.x + t0.x, 0.f);
                ar[1] = fmaxf(ar[1] * s0.y + t0.y, 0.f);
                ar[2] = fmaxf(ar[2] * s0.z + t0.z, 0.f);
                ar[3] = fmaxf(ar[3] * s0.w + t0.w, 0.f);
                ar[4] = fmaxf(ar[4] * s1.x + t1.x, 0.f);
                ar[5] = fmaxf(ar[5] * s1.y + t1.y, 0.f);
                ar[6] = fmaxf(ar[6] * s1.z + t1.z, 0.f);
                ar[7] = fmaxf(ar[7] * s1.w + t1.w, 0.f);
            } else {
#pragma unroll
                for (int j = 0; j < 8; j++) {
                    int k = gk + j;
                    if (k < DIM)
                        ar[j] = fmaxf(ar[j] * g_coef[k] + g_coef[DIM + k], 0.f);
                }
            }
        }
    };
    auto loadB = [&](int kt) {
        int gk2 = kt * 16 + b_k;
        int gn = n0 + b_n;
        if (gk2 < DIM && gn + 3 < DIM) {
            const float4 v = *(const float4*)&Wl[gk2 * DIM + gn];
            br[0] = v.x; br[1] = v.y; br[2] = v.z; br[3] = v.w;
        } else {
#pragma unroll
            for (int j = 0; j < 4; j++)
                br[j] = (gk2 < DIM && gn + j < DIM) ? Wl[gk2 * DIM + gn + j]
                                                    : 0.f;
        }
    };
    auto stage = [&](int buf) {
        uint2* ap = As + buf * A_TILE + a_k * A_STR + a_m;
#pragma unroll
        for (int j = 0; j < 8; j++) ap[j * A_STR] = split_tf32(ar[j]);
        uint2* bp = Bs + buf * B_TILE + b_k * B_STR + b_n;
#pragma unroll
        for (int j = 0; j < 4; j++) bp[j] = split_tf32(br[j]);
    };

    loadA(0); loadB(0); stage(0);
    __syncthreads();

#pragma unroll 1
    for (int kt = 0; kt < NKT; kt++) {
        const int buf = kt & 1;
        if (kt < NKT - 1) { loadA(kt + 1); loadB(kt + 1); }

        const uint2* Ab = As + buf * A_TILE;
        const uint2* Bb = Bs + buf * B_TILE;
#pragma unroll
        for (int kb = 0; kb < 16; kb += 8) {
            uint2 a0[2], a1[2], a2[2], a3[2];
#pragma unroll
            for (int im = 0; im < 2; im++) {
                int mo = wm * 32 + im * 16;
                a0[im] = Ab[(kb + tg) * A_STR + mo + g];
                a1[im] = Ab[(kb + tg) * A_STR + mo + g + 8];
                a2[im] = Ab[(kb + tg + 4) * A_STR + mo + g];
                a3[im] = Ab[(kb + tg + 4) * A_STR + mo + g + 8];
            }
            uint2 b0[4], b1[4];
#pragma unroll
            for (int in = 0; in < 4; in++) {
                int no = wn * 32 + in * 8;
                b0[in] = Bb[(kb + tg) * B_STR + no + g];
                b1[in] = Bb[(kb + tg + 4) * B_STR + no + g];
            }
#pragma unroll
            for (int im = 0; im < 2; im++)
#pragma unroll
                for (int in = 0; in < 4; in++) {
                    MMA_TF32(c[im][in], a0[im].y, a1[im].y, a2[im].y, a3[im].y,
                             b0[in].x, b1[in].x);
                    MMA_TF32(c[im][in], a0[im].x, a1[im].x, a2[im].x, a3[im].x,
                             b0[in].y, b1[in].y);
                    MMA_TF32(c[im][in], a0[im].x, a1[im].x, a2[im].x, a3[im].x,
                             b0[in].x, b1[in].x);
                }
        }

        if (kt < NKT - 1) stage(buf ^ 1);
        __syncthreads();
    }

    // ---- epilogue: write g_hw ----
#pragma unroll
    for (int in = 0; in < 4; in++) {
        int ncol = n0 + wn * 32 + in * 8 + 2 * tg;
        if (ncol >= DIM) continue;
#pragma unroll
        for (int im = 0; im < 2; im++) {
            int r0 = m0 + wm * 32 + im * 16 + g;
            if (r0 < N_NODES)
                *(float2*)&g_hw[r0 * DIM + ncol] =
                    make_float2(c[im][in][0], c[im][in][1]);
            int r1 = r0 + 8;
            if (r1 < N_NODES)
                *(float2*)&g_hw[r1 * DIM + ncol] =
                    make_float2(c[im][in][2], c[im][in][3]);
        }
    }
}

// ---------------- CSR aggregation --------------------------------------------
__global__ __launch_bounds__(128)
void agg_kernel(const float* __restrict__ bl,
                const float* __restrict__ e1,
                const float* __restrict__ e2,
                int l) {
    __shared__ float s_em[9];
    __shared__ int s_pk[128];
    const int n = blockIdx.x;
    const int tid = threadIdx.x;
    if (tid < 9) s_em[tid] = e1[l * 5 + tid / 3] + e2[l * 3 + tid % 3];
    const float selfE = e1[l * 5 + 4] + e2[l * 3 + 0];
    __syncthreads();
    const int start = g_start[n], end = g_start[n + 1];
    const int d0 = tid, d1 = tid + 128, d2 = tid + 256;
    float a0 = 0.f, a1 = 0.f, a2 = 0.f;
    for (int base = start; base < end; base += 128) {
        int idx = base + tid;
        if (idx < end) s_pk[tid] = g_csr[idx];
        __syncthreads();
        int cnt = min(128, end - base);
#pragma unroll 4
        for (int i = 0; i < cnt; i++) {
            int pk = s_pk[i];
            const float* p = g_hw + (pk & 0xFFFF) * DIM;
            float em = s_em[pk >> 16];
            a0 += p[d0] + em;
            a1 += p[d1] + em;
            if (d2 < DIM) a2 += p[d2] + em;
        }
        __syncthreads();
    }
    const float* hp = g_hw + n * DIM;
    float* op = g_agg + n * DIM;
    op[d0] = a0 + hp[d0] + bl[d0] + selfE;
    op[d1] = a1 + hp[d1] + bl[d1] + selfE;
    if (d2 < DIM) op[d2] = a2 + hp[d2] + bl[d2] + selfE;
}

// ---------------- batch norm stats + coefficients ----------------------------
#define STAT_ROWS 50
__global__ void stats_kernel(int l) {
    int tid = threadIdx.x;            // 128
    int r0 = blockIdx.x * STAT_ROWS;
    float* st = &g_stats[l * 2 * DIM];
    int c0 = tid, c1 = tid + 128, c2 = tid + 256;
    float s0 = 0, q0 = 0, s1 = 0, q1 = 0, s2 = 0, q2 = 0;
    int rend = r0 + STAT_ROWS;
    if (rend > N_NODES) rend = N_NODES;
    for (int r = r0; r < rend; r++) {
        const float* p = &g_agg[(long)r * DIM];
        float v0 = p[c0]; s0 += v0; q0 += v0 * v0;
        float v1 = p[c1]; s1 += v1; q1 += v1 * v1;
        if (c2 < DIM) { float v2 = p[c2]; s2 += v2; q2 += v2 * v2; }
    }
    atomicAdd(&st[c0], s0);
    atomicAdd(&st[DIM + c0], q0);
    atomicAdd(&st[c1], s1);
    atomicAdd(&st[DIM + c1], q1);
    if (c2 < DIM) {
        atomicAdd(&st[c2], s2);
        atomicAdd(&st[DIM + c2], q2);
    }
}

__global__ void coef_kernel(const float* __restrict__ gamma,
                            const float* __restrict__ beta, int l) {
    int d = blockIdx.x * blockDim.x + threadIdx.x;
    if (d >= DIM) return;
    const float* st = &g_stats[l * 2 * DIM];
    const float inv_n = 1.0f / (float)N_NODES;
    float mu = st[d] * inv_n;
    float var = st[DIM + d] * inv_n - mu * mu;
    float s = rsqrtf(var + EPS) * gamma[l * DIM + d];
    g_coef[d] = s;
    g_coef[DIM + d] = beta[l * DIM + d] - mu * s;
}

// ---------------- pool (applies final BN; batch sorted -> segments) ----------
__global__ void gbound_kernel(const int* __restrict__ batch) {
    int g = blockIdx.x * blockDim.x + threadIdx.x;
    if (g > N_GRAPHS) return;
    int lo = 0, hi = N_NODES;
    while (lo < hi) {
        int mid = (lo + hi) >> 1;
        if (batch[mid] < g) lo = mid + 1; else hi = mid;
    }
    g_gstart[g] = lo;
}

__global__ __launch_bounds__(128)
void pool_kernel() {
    const int g = blockIdx.x;
    const int tid = threadIdx.x;
    const int gs = g_gstart[g], ge = g_gstart[g + 1];
    const int d0 = tid, d1 = tid + 128, d2 = tid + 256;
    float a0 = 0.f, a1 = 0.f, a2 = 0.f;
#pragma unroll 2
    for (int r = gs; r < ge; r++) {
        const float* p = g_agg + r * DIM;
        a0 += p[d0];
        a1 += p[d1];
        if (d2 < DIM) a2 += p[d2];
    }
    float inv = 1.0f / fmaxf((float)(ge - gs), 1.0f);
    float* op = g_hg + g * DIM;
    // mean(bn(x)) = mean(x)*scale + shift  (affine commutes with mean)
    op[d0] = (a0 * inv) * g_coef[d0] + g_coef[DIM + d0];
    op[d1] = (a1 * inv) * g_coef[d1] + g_coef[DIM + d1];
    if (d2 < DIM) op[d2] = (a2 * inv) * g_coef[d2] + g_coef[DIM + d2];
}

// ---------------- head MLPs --------------------------------------------------
__global__ void gemm_feat(const float* __restrict__ fw,
                          const float* __restrict__ fb,
                          float* __restrict__ hfeat) {
    __shared__ float sh[DIM];
    int g = blockIdx.x;
    int t = threadIdx.x;  // 256
    for (int k = t; k < DIM; k += FEAT) sh[k] = g_hg[g * DIM + k];
    __syncthreads();
    float acc = fb[t];
    for (int k = 0; k < DIM; k++) acc += sh[k] * fw[k * FEAT + t];
    hfeat[g * FEAT + t] = acc;
}

__global__ void gemm_mlp1(const float* __restrict__ hfeat,
                          const float* __restrict__ w1,
                          const float* __restrict__ b1) {
    __shared__ float sh[FEAT];
    int g = blockIdx.x;
    int t = threadIdx.x;  // 256
    sh[t] = hfeat[g * FEAT + t];
    __syncthreads();
    float acc = b1[t];
    for (int k = 0; k < FEAT; k++) acc += sh[k] * w1[k * FEAT + t];
    g_hid[g * FEAT + t] = fmaxf(acc, 0.f);
}

__global__ void gemm_mlp2(const float* __restrict__ w2,
                          const float* __restrict__ b2,
                          float* __restrict__ out) {
    __shared__ float sh[FEAT];
    int g = blockIdx.x;
    int t = threadIdx.x;  // 128
    sh[t] = g_hid[g * FEAT + t];
    sh[t + 128] = g_hid[g * FEAT + t + 128];
    __syncthreads();
    float acc = b2[t];
    for (int k = 0; k < FEAT; k++) acc += sh[k] * w2[k * 128 + t];
    out[g * 128 + t] = acc;
}

// ---------------- launch -----------------------------------------------------
extern "C" void kernel_launch(void* const* d_in, const int* in_sizes, int n_in,
                              void* d_out, int out_size) {
    const int*   x     = (const int*)d_in[0];
    const int*   ei    = (const int*)d_in[1];
    const int*   ea    = (const int*)d_in[2];
    const int*   batch = (const int*)d_in[3];
    const float* emb1  = (const float*)d_in[4];
    const float* emb2  = (const float*)d_in[5];
    const float* W     = (const float*)d_in[6];
    const float* b     = (const float*)d_in[7];
    const float* e1    = (const float*)d_in[8];
    const float* e2    = (const float*)d_in[9];
    const float* gamma = (const float*)d_in[10];
    const float* beta  = (const float*)d_in[11];
    const float* fw    = (const float*)d_in[12];
    const float* fb    = (const float*)d_in[13];
    const float* w1    = (const float*)d_in[14];
    const float* b1    = (const float*)d_in[15];
    const float* w2    = (const float*)d_in[16];
    const float* b2    = (const float*)d_in[17];

    float* hfeat_out = (float*)d_out;
    float* final_out = (float*)d_out + N_GRAPHS * FEAT;

    static int smem_set = 0;
    if (!smem_set) {
        cudaFuncSetAttribute(gemm_layer_tc,
                             cudaFuncAttributeMaxDynamicSharedMemorySize,
                             SMEM_BYTES);
        smem_set = 1;
    }

    // device pointers to globals (for src argument)
    float* d_h;  cudaGetSymbolAddress((void**)&d_h, g_h);
    float* d_agg; cudaGetSymbolAddress((void**)&d_agg, g_agg);

    dim3 ggrid((DIM + 63) / 64, (N_NODES + 127) / 128);

    // Launch order puts gemm_layer_tc at position #4 for ncu attribution.
    embed_kernel<<<(N_NODES * DIM + 255) / 256, 256>>>(x, emb1, emb2);  // 1
    hist_kernel<<<(N_EDGES + 255) / 256, 256>>>(ei);                    // 2
    scan1_kernel<<<NBLK_SCAN, 256>>>();                                 // 3
    gemm_layer_tc<<<ggrid, 256, SMEM_BYTES>>>(W, d_h, 0);               // 4 (l=0)
    scan2_kernel<<<1, 256>>>();                                         // 5
    scan3_kernel<<<(N_NODES + 255) / 256, 256>>>();                     // 6
    fill_kernel<<<(N_EDGES + 255) / 256, 256>>>(ei, ea);                // 7

    for (int l = 0; l < N_LAYERS; l++) {
        if (l > 0)
            gemm_layer_tc<<<ggrid, 256, SMEM_BYTES>>>(
                W + (long)l * DIM * DIM, d_agg, 1);
        agg_kernel<<<N_NODES, 128>>>(b + l * DIM, e1, e2, l);
        stats_kernel<<<N_NODES / STAT_ROWS, 128>>>(l);
        coef_kernel<<<2, 256>>>(gamma, beta, l);
    }

    gbound_kernel<<<(N_GRAPHS + 256) / 256, 256>>>(batch);
    pool_kernel<<<N_GRAPHS, 128>>>();

    gemm_feat<<<N_GRAPHS, FEAT>>>(fw, fb, hfeat_out);
    gemm_mlp1<<<N_GRAPHS, FEAT>>>(hfeat_out, w1, b1);
    gemm_mlp2<<<N_GRAPHS, 128>>>(w2, b2, final_out);
}

// round 6
// speedup vs baseline: 1.0984x; 1.0984x over previous
#include <cuda_runtime.h>
#include <cuda_bf16.h>

#define N_NODES 50000
#define N_EDGES 800000
#define N_GRAPHS 1024
#define DIM 300
#define N_LAYERS 5
#define FEAT 256
#define EPS 1e-5f
#define NBLK_SCAN ((N_NODES + 255) / 256)   // 196

// ---------------- scratch (static device globals; no allocation) -------------
__device__ float g_h[N_NODES * DIM];     // embed output (layer-0 input)
__device__ float g_hw[N_NODES * DIM];    // h @ W[l]
__device__ float g_agg[N_NODES * DIM];   // pre-BN accumulation
__device__ float g_stats[N_LAYERS * 2 * DIM];
__device__ float g_coef[2 * DIM];        // current layer BN scale/shift
__device__ float g_hg[N_GRAPHS * DIM];
__device__ float g_hid[N_GRAPHS * FEAT];
// CSR build
__device__ int g_deg[N_NODES];
__device__ int g_incl[N_NODES];
__device__ int g_bsum[NBLK_SCAN];
__device__ int g_boff[NBLK_SCAN];
__device__ int g_cursor[N_NODES];
__device__ int g_start[N_NODES + 1];
__device__ int g_csr[N_EDGES];           // row | (attr<<16)
__device__ int g_gstart[N_GRAPHS + 1];

// ---------------- node embedding + zero deg/stats ----------------------------
__global__ void embed_kernel(const int* __restrict__ x,
                             const float* __restrict__ emb1,
                             const float* __restrict__ emb2) {
    int i = blockIdx.x * blockDim.x + threadIdx.x;
    if (i < N_LAYERS * 2 * DIM) g_stats[i] = 0.f;
    if (i < N_NODES) g_deg[i] = 0;
    if (i >= N_NODES * DIM) return;
    int n = i / DIM, d = i - n * DIM;
    int a = x[2 * n], c = x[2 * n + 1];
    g_h[i] = emb1[a * DIM + d] + emb2[c * DIM + d];
}

// ---------------- CSR build ---------------------------------------------------
__global__ void hist_kernel(const int* __restrict__ ei) {
    int e = blockIdx.x * blockDim.x + threadIdx.x;
    if (e >= N_EDGES) return;
    atomicAdd(&g_deg[ei[N_EDGES + e]], 1);
}

__global__ void scan1_kernel() {
    __shared__ int s[256];
    int tid = threadIdx.x;
    int i = blockIdx.x * 256 + tid;
    int v = (i < N_NODES) ? g_deg[i] : 0;
    s[tid] = v;
    __syncthreads();
#pragma unroll
    for (int off = 1; off < 256; off <<= 1) {
        int t = (tid >= off) ? s[tid - off] : 0;
        __syncthreads();
        s[tid] += t;
        __syncthreads();
    }
    if (i < N_NODES) g_incl[i] = s[tid];
    if (tid == 255) g_bsum[blockIdx.x] = s[255];
}

__global__ void scan2_kernel() {
    __shared__ int s[256];
    int tid = threadIdx.x;
    s[tid] = (tid < NBLK_SCAN) ? g_bsum[tid] : 0;
    __syncthreads();
#pragma unroll
    for (int off = 1; off < 256; off <<= 1) {
        int t = (tid >= off) ? s[tid - off] : 0;
        __syncthreads();
        s[tid] += t;
        __syncthreads();
    }
    if (tid < NBLK_SCAN) g_boff[tid] = s[tid] - g_bsum[tid];
}

__global__ void scan3_kernel() {
    int i = blockIdx.x * blockDim.x + threadIdx.x;
    if (i >= N_NODES) return;
    g_start[i + 1] = g_incl[i] + g_boff[i >> 8];
    g_cursor[i] = 0;
    if (i == 0) g_start[0] = 0;
}

__global__ void fill_kernel(const int* __restrict__ ei,
                            const int* __restrict__ ea) {
    int e = blockIdx.x * blockDim.x + threadIdx.x;
    if (e >= N_EDGES) return;
    int row = ei[e];
    int col = ei[N_EDGES + e];
    int attr = ea[2 * e] * 3 + ea[2 * e + 1];  // 0..8
    int pos = g_start[col] + atomicAdd(&g_cursor[col], 1);
    g_csr[pos] = row | (attr << 16);
}

// ---------------- 3xTF32 tensor-core GEMM with fused BN+ReLU on A ------------
__device__ __forceinline__ unsigned f2tf32(float x) {
    unsigned u;
    asm("cvt.rna.tf32.f32 %0, %1;" : "=r"(u) : "f"(x));
    return u;
}

#define MMA_TF32(cc, A0, A1, A2, A3, B0, B1)                                   \
    asm volatile(                                                              \
        "mma.sync.aligned.m16n8k8.row.col.f32.tf32.tf32.f32 "                  \
        "{%0,%1,%2,%3},{%4,%5,%6,%7},{%8,%9},{%0,%1,%2,%3};"                   \
        : "+f"(cc[0]), "+f"(cc[1]), "+f"(cc[2]), "+f"(cc[3])                   \
        : "r"(A0), "r"(A1), "r"(A2), "r"(A3), "r"(B0), "r"(B1));

#define NKT 38  // ceil(300/8)

__global__ __launch_bounds__(256)
void gemm_layer_tc(const float* __restrict__ Wl,   // [DIM, DIM] row-major
                   const float* __restrict__ src,  // g_h (l=0) or g_agg
                   int apply_bn) {
    // 4-byte arrays, conflict-free: bank = (8*tg + g) mod 32 is a permutation.
    __shared__ unsigned Ah[2][8][136], Al[2][8][136];  // [buf][k][m]
    __shared__ unsigned Bh[2][8][72],  Bl[2][8][72];   // [buf][k][n]

    const int tid = threadIdx.x;
    const int lane = tid & 31;
    const int warp = tid >> 5;
    const int g = lane >> 2;      // 0..7
    const int tg = lane & 3;      // 0..3
    const int wm = warp >> 1;     // 0..3 (m)
    const int wn = warp & 1;      // 0..1 (n)
    const int m0 = blockIdx.y * 128;
    const int n0 = blockIdx.x * 64;

    float c[2][4][4];
#pragma unroll
    for (int im = 0; im < 2; im++)
#pragma unroll
        for (int in = 0; in < 4; in++)
#pragma unroll
            for (int j = 0; j < 4; j++) c[im][in][j] = 0.f;

    const int a_m = tid >> 1;          // 0..127
    const int a_k = (tid & 1) * 4;     // 0 or 4
    const int b_k = tid >> 5;          // 0..7
    const int b_n = (tid & 31) * 2;    // 0..62
    const int gm = m0 + a_m;

    float ar[4], br[2];

    auto loadA = [&](int kt) {
        int gk = kt * 8 + a_k;
        if (gm < N_NODES && gk + 3 < DIM) {
            const float4 v = *(const float4*)&src[gm * DIM + gk];
            ar[0] = v.x; ar[1] = v.y; ar[2] = v.z; ar[3] = v.w;
            if (apply_bn) {
                const float4 s = *(const float4*)&g_coef[gk];
                const float4 t = *(const float4*)&g_coef[DIM + gk];
                ar[0] = fmaxf(ar[0] * s.x + t.x, 0.f);
                ar[1] = fmaxf(ar[1] * s.y + t.y, 0.f);
                ar[2] = fmaxf(ar[2] * s.z + t.z, 0.f);
                ar[3] = fmaxf(ar[3] * s.w + t.w, 0.f);
            }
        } else {
#pragma unroll
            for (int j = 0; j < 4; j++) {
                int k = gk + j;
                float v = (gm < N_NODES && k < DIM) ? src[gm * DIM + k] : 0.f;
                if (apply_bn && k < DIM)
                    v = fmaxf(v * g_coef[k] + g_coef[DIM + k], 0.f);
                ar[j] = v;
            }
        }
    };
    auto loadB = [&](int kt) {
        int gk2 = kt * 8 + b_k;
        int gn = n0 + b_n;
        if (gk2 < DIM && gn + 1 < DIM) {
            const float2 v = *(const float2*)&Wl[gk2 * DIM + gn];
            br[0] = v.x; br[1] = v.y;
        } else {
#pragma unroll
            for (int j = 0; j < 2; j++)
                br[j] = (gk2 < DIM && gn + j < DIM) ? Wl[gk2 * DIM + gn + j]
                                                    : 0.f;
        }
    };
    auto stage = [&](int buf) {
#pragma unroll
        for (int j = 0; j < 4; j++) {
            unsigned hi = f2tf32(ar[j]);
            Ah[buf][a_k + j][a_m] = hi;
            Al[buf][a_k + j][a_m] = f2tf32(ar[j] - __uint_as_float(hi));
        }
#pragma unroll
        for (int j = 0; j < 2; j++) {
            unsigned hi = f2tf32(br[j]);
            Bh[buf][b_k][b_n + j] = hi;
            Bl[buf][b_k][b_n + j] = f2tf32(br[j] - __uint_as_float(hi));
        }
    };

    loadA(0); loadB(0); stage(0);
    __syncthreads();

#pragma unroll 1
    for (int kt = 0; kt < NKT; kt++) {
        const int buf = kt & 1;
        if (kt < NKT - 1) { loadA(kt + 1); loadB(kt + 1); }

        {
            unsigned ah0[2], ah1[2], ah2[2], ah3[2];
            unsigned al0[2], al1[2], al2[2], al3[2];
#pragma unroll
            for (int im = 0; im < 2; im++) {
                int mo = wm * 32 + im * 16;
                ah0[im] = Ah[buf][tg][mo + g];
                ah1[im] = Ah[buf][tg][mo + g + 8];
                ah2[im] = Ah[buf][tg + 4][mo + g];
                ah3[im] = Ah[buf][tg + 4][mo + g + 8];
                al0[im] = Al[buf][tg][mo + g];
                al1[im] = Al[buf][tg][mo + g + 8];
                al2[im] = Al[buf][tg + 4][mo + g];
                al3[im] = Al[buf][tg + 4][mo + g + 8];
            }
            unsigned bh0[4], bh1[4], bl0[4], bl1[4];
#pragma unroll
            for (int in = 0; in < 4; in++) {
                int no = wn * 32 + in * 8;
                bh0[in] = Bh[buf][tg][no + g];
                bh1[in] = Bh[buf][tg + 4][no + g];
                bl0[in] = Bl[buf][tg][no + g];
                bl1[in] = Bl[buf][tg + 4][no + g];
            }
#pragma unroll
            for (int im = 0; im < 2; im++)
#pragma unroll
                for (int in = 0; in < 4; in++) {
                    MMA_TF32(c[im][in], al0[im], al1[im], al2[im], al3[im],
                             bh0[in], bh1[in]);
                    MMA_TF32(c[im][in], ah0[im], ah1[im], ah2[im], ah3[im],
                             bl0[in], bl1[in]);
                    MMA_TF32(c[im][in], ah0[im], ah1[im], ah2[im], ah3[im],
                             bh0[in], bh1[in]);
                }
        }

        if (kt < NKT - 1) stage(buf ^ 1);
        __syncthreads();
    }

    // ---- epilogue: write g_hw ----
#pragma unroll
    for (int in = 0; in < 4; in++) {
        int ncol = n0 + wn * 32 + in * 8 + 2 * tg;
        if (ncol >= DIM) continue;
#pragma unroll
        for (int im = 0; im < 2; im++) {
            int r0 = m0 + wm * 32 + im * 16 + g;
            if (r0 < N_NODES)
                *(float2*)&g_hw[r0 * DIM + ncol] =
                    make_float2(c[im][in][0], c[im][in][1]);
            int r1 = r0 + 8;
            if (r1 < N_NODES)
                *(float2*)&g_hw[r1 * DIM + ncol] =
                    make_float2(c[im][in][2], c[im][in][3]);
        }
    }
}

// ---------------- CSR aggregation --------------------------------------------
__global__ __launch_bounds__(128)
void agg_kernel(const float* __restrict__ bl,
                const float* __restrict__ e1,
                const float* __restrict__ e2,
                int l) {
    __shared__ float s_em[9];
    __shared__ int s_pk[128];
    const int n = blockIdx.x;
    const int tid = threadIdx.x;
    if (tid < 9) s_em[tid] = e1[l * 5 + tid / 3] + e2[l * 3 + tid % 3];
    const float selfE = e1[l * 5 + 4] + e2[l * 3 + 0];
    __syncthreads();
    const int start = g_start[n], end = g_start[n + 1];
    const int d0 = tid, d1 = tid + 128, d2 = tid + 256;
    float a0 = 0.f, a1 = 0.f, a2 = 0.f;
    for (int base = start; base < end; base += 128) {
        int idx = base + tid;
        if (idx < end) s_pk[tid] = g_csr[idx];
        __syncthreads();
        int cnt = min(128, end - base);
#pragma unroll 4
        for (int i = 0; i < cnt; i++) {
            int pk = s_pk[i];
            const float* p = g_hw + (pk & 0xFFFF) * DIM;
            float em = s_em[pk >> 16];
            a0 += p[d0] + em;
            a1 += p[d1] + em;
            if (d2 < DIM) a2 += p[d2] + em;
        }
        __syncthreads();
    }
    const float* hp = g_hw + n * DIM;
    float* op = g_agg + n * DIM;
    op[d0] = a0 + hp[d0] + bl[d0] + selfE;
    op[d1] = a1 + hp[d1] + bl[d1] + selfE;
    if (d2 < DIM) op[d2] = a2 + hp[d2] + bl[d2] + selfE;
}

// ---------------- batch norm stats + coefficients ----------------------------
#define STAT_ROWS 50
__global__ void stats_kernel(int l) {
    int tid = threadIdx.x;            // 128
    int r0 = blockIdx.x * STAT_ROWS;
    float* st = &g_stats[l * 2 * DIM];
    int c0 = tid, c1 = tid + 128, c2 = tid + 256;
    float s0 = 0, q0 = 0, s1 = 0, q1 = 0, s2 = 0, q2 = 0;
    int rend = r0 + STAT_ROWS;
    if (rend > N_NODES) rend = N_NODES;
    for (int r = r0; r < rend; r++) {
        const float* p = &g_agg[(long)r * DIM];
        float v0 = p[c0]; s0 += v0; q0 += v0 * v0;
        float v1 = p[c1]; s1 += v1; q1 += v1 * v1;
        if (c2 < DIM) { float v2 = p[c2]; s2 += v2; q2 += v2 * v2; }
    }
    atomicAdd(&st[c0], s0);
    atomicAdd(&st[DIM + c0], q0);
    atomicAdd(&st[c1], s1);
    atomicAdd(&st[DIM + c1], q1);
    if (c2 < DIM) {
        atomicAdd(&st[c2], s2);
        atomicAdd(&st[DIM + c2], q2);
    }
}

__global__ void coef_kernel(const float* __restrict__ gamma,
                            const float* __restrict__ beta, int l) {
    int d = blockIdx.x * blockDim.x + threadIdx.x;
    if (d >= DIM) return;
    const float* st = &g_stats[l * 2 * DIM];
    const float inv_n = 1.0f / (float)N_NODES;
    float mu = st[d] * inv_n;
    float var = st[DIM + d] * inv_n - mu * mu;
    float s = rsqrtf(var + EPS) * gamma[l * DIM + d];
    g_coef[d] = s;
    g_coef[DIM + d] = beta[l * DIM + d] - mu * s;
}

// ---------------- pool (applies final BN; batch sorted -> segments) ----------
__global__ void gbound_kernel(const int* __restrict__ batch) {
    int g = blockIdx.x * blockDim.x + threadIdx.x;
    if (g > N_GRAPHS) return;
    int lo = 0, hi = N_NODES;
    while (lo < hi) {
        int mid = (lo + hi) >> 1;
        if (batch[mid] < g) lo = mid + 1; else hi = mid;
    }
    g_gstart[g] = lo;
}

__global__ __launch_bounds__(128)
void pool_kernel() {
    const int g = blockIdx.x;
    const int tid = threadIdx.x;
    const int gs = g_gstart[g], ge = g_gstart[g + 1];
    const int d0 = tid, d1 = tid + 128, d2 = tid + 256;
    float a0 = 0.f, a1 = 0.f, a2 = 0.f;
#pragma unroll 2
    for (int r = gs; r < ge; r++) {
        const float* p = g_agg + r * DIM;
        a0 += p[d0];
        a1 += p[d1];
        if (d2 < DIM) a2 += p[d2];
    }
    float inv = 1.0f / fmaxf((float)(ge - gs), 1.0f);
    float* op = g_hg + g * DIM;
    // mean(bn(x)) = mean(x)*scale + shift  (affine commutes with mean)
    op[d0] = (a0 * inv) * g_coef[d0] + g_coef[DIM + d0];
    op[d1] = (a1 * inv) * g_coef[d1] + g_coef[DIM + d1];
    if (d2 < DIM) op[d2] = (a2 * inv) * g_coef[d2] + g_coef[DIM + d2];
}

// ---------------- head MLPs --------------------------------------------------
__global__ void gemm_feat(const float* __restrict__ fw,
                          const float* __restrict__ fb,
                          float* __restrict__ hfeat) {
    __shared__ float sh[DIM];
    int g = blockIdx.x;
    int t = threadIdx.x;  // 256
    for (int k = t; k < DIM; k += FEAT) sh[k] = g_hg[g * DIM + k];
    __syncthreads();
    float acc = fb[t];
    for (int k = 0; k < DIM; k++) acc += sh[k] * fw[k * FEAT + t];
    hfeat[g * FEAT + t] = acc;
}

__global__ void gemm_mlp1(const float* __restrict__ hfeat,
                          const float* __restrict__ w1,
                          const float* __restrict__ b1) {
    __shared__ float sh[FEAT];
    int g = blockIdx.x;
    int t = threadIdx.x;  // 256
    sh[t] = hfeat[g * FEAT + t];
    __syncthreads();
    float acc = b1[t];
    for (int k = 0; k < FEAT; k++) acc += sh[k] * w1[k * FEAT + t];
    g_hid[g * FEAT + t] = fmaxf(acc, 0.f);
}

__global__ void gemm_mlp2(const float* __restrict__ w2,
                          const float* __restrict__ b2,
                          float* __restrict__ out) {
    __shared__ float sh[FEAT];
    int g = blockIdx.x;
    int t = threadIdx.x;  // 128
    sh[t] = g_hid[g * FEAT + t];
    sh[t + 128] = g_hid[g * FEAT + t + 128];
    __syncthreads();
    float acc = b2[t];
    for (int k = 0; k < FEAT; k++) acc += sh[k] * w2[k * 128 + t];
    out[g * 128 + t] = acc;
}

// ---------------- launch -----------------------------------------------------
extern "C" void kernel_launch(void* const* d_in, const int* in_sizes, int n_in,
                              void* d_out, int out_size) {
    const int*   x     = (const int*)d_in[0];
    const int*   ei    = (const int*)d_in[1];
    const int*   ea    = (const int*)d_in[2];
    const int*   batch = (const int*)d_in[3];
    const float* emb1  = (const float*)d_in[4];
    const float* emb2  = (const float*)d_in[5];
    const float* W     = (const float*)d_in[6];
    const float* b     = (const float*)d_in[7];
    const float* e1    = (const float*)d_in[8];
    const float* e2    = (const float*)d_in[9];
    const float* gamma = (const float*)d_in[10];
    const float* beta  = (const float*)d_in[11];
    const float* fw    = (const float*)d_in[12];
    const float* fb    = (const float*)d_in[13];
    const float* w1    = (const float*)d_in[14];
    const float* b1    = (const float*)d_in[15];
    const float* w2    = (const float*)d_in[16];
    const float* b2    = (const float*)d_in[17];

    float* hfeat_out = (float*)d_out;
    float* final_out = (float*)d_out + N_GRAPHS * FEAT;

    float* d_h;   cudaGetSymbolAddress((void**)&d_h, g_h);
    float* d_agg; cudaGetSymbolAddress((void**)&d_agg, g_agg);

    dim3 ggrid((DIM + 63) / 64, (N_NODES + 127) / 128);

    // Launch order puts gemm_layer_tc at position #4 for ncu attribution.
    embed_kernel<<<(N_NODES * DIM + 255) / 256, 256>>>(x, emb1, emb2);  // 1
    hist_kernel<<<(N_EDGES + 255) / 256, 256>>>(ei);                    // 2
    scan1_kernel<<<NBLK_SCAN, 256>>>();                                 // 3
    gemm_layer_tc<<<ggrid, 256>>>(W, d_h, 0);                           // 4 (l=0)
    scan2_kernel<<<1, 256>>>();                                         // 5
    scan3_kernel<<<(N_NODES + 255) / 256, 256>>>();                     // 6
    fill_kernel<<<(N_EDGES + 255) / 256, 256>>>(ei, ea);                // 7

    for (int l = 0; l < N_LAYERS; l++) {
        if (l > 0)
            gemm_layer_tc<<<ggrid, 256>>>(W + (long)l * DIM * DIM, d_agg, 1);
        agg_kernel<<<N_NODES, 128>>>(b + l * DIM, e1, e2, l);
        stats_kernel<<<N_NODES / STAT_ROWS, 128>>>(l);
        coef_kernel<<<2, 256>>>(gamma, beta, l);
    }

    gbound_kernel<<<(N_GRAPHS + 256) / 256, 256>>>(batch);
    pool_kernel<<<N_GRAPHS, 128>>>();

    gemm_feat<<<N_GRAPHS, FEAT>>>(fw, fb, hfeat_out);
    gemm_mlp1<<<N_GRAPHS, FEAT>>>(hfeat_out, w1, b1);
    gemm_mlp2<<<N_GRAPHS, 128>>>(w2, b2, final_out);
}

// round 7
// speedup vs baseline: 1.3675x; 1.2450x over previous
#include <cuda_runtime.h>
#include <cuda_bf16.h>

#define N_NODES 50000
#define N_EDGES 800000
#define N_GRAPHS 1024
#define DIM 300
#define N_LAYERS 5
#define FEAT 256
#define EPS 1e-5f
#define NBLK_SCAN ((N_NODES + 255) / 256)   // 196

// ---------------- scratch (static device globals; no allocation) -------------
__device__ float g_h[N_NODES * DIM];     // embed output (layer-0 input)
__device__ float g_hw[N_NODES * DIM];    // h @ W[l]
__device__ float g_agg[N_NODES * DIM];   // pre-BN accumulation
__device__ float g_stats[N_LAYERS * 2 * DIM];
__device__ float g_coef[2 * DIM];        // current layer BN scale/shift
__device__ float g_hg[N_GRAPHS * DIM];
__device__ float g_hid[N_GRAPHS * FEAT];
// CSR build
__device__ int g_deg[N_NODES];
__device__ int g_incl[N_NODES];
__device__ int g_bsum[NBLK_SCAN];
__device__ int g_boff[NBLK_SCAN];
__device__ int g_cursor[N_NODES];
__device__ int g_start[N_NODES + 1];
__device__ int g_csr[N_EDGES];           // row | (attr<<16)
__device__ int g_gstart[N_GRAPHS + 1];

// ---------------- node embedding + zero deg/stats ----------------------------
__global__ void embed_kernel(const int* __restrict__ x,
                             const float* __restrict__ emb1,
                             const float* __restrict__ emb2) {
    int i = blockIdx.x * blockDim.x + threadIdx.x;
    if (i < N_LAYERS * 2 * DIM) g_stats[i] = 0.f;
    if (i < N_NODES) g_deg[i] = 0;
    if (i >= N_NODES * DIM) return;
    int n = i / DIM, d = i - n * DIM;
    int a = x[2 * n], c = x[2 * n + 1];
    g_h[i] = emb1[a * DIM + d] + emb2[c * DIM + d];
}

// ---------------- CSR build ---------------------------------------------------
__global__ void hist_kernel(const int* __restrict__ ei) {
    int e = blockIdx.x * blockDim.x + threadIdx.x;
    if (e >= N_EDGES) return;
    atomicAdd(&g_deg[ei[N_EDGES + e]], 1);
}

__global__ void scan1_kernel() {
    __shared__ int s[256];
    int tid = threadIdx.x;
    int i = blockIdx.x * 256 + tid;
    int v = (i < N_NODES) ? g_deg[i] : 0;
    s[tid] = v;
    __syncthreads();
#pragma unroll
    for (int off = 1; off < 256; off <<= 1) {
        int t = (tid >= off) ? s[tid - off] : 0;
        __syncthreads();
        s[tid] += t;
        __syncthreads();
    }
    if (i < N_NODES) g_incl[i] = s[tid];
    if (tid == 255) g_bsum[blockIdx.x] = s[255];
}

__global__ void scan2_kernel() {
    __shared__ int s[256];
    int tid = threadIdx.x;
    s[tid] = (tid < NBLK_SCAN) ? g_bsum[tid] : 0;
    __syncthreads();
#pragma unroll
    for (int off = 1; off < 256; off <<= 1) {
        int t = (tid >= off) ? s[tid - off] : 0;
        __syncthreads();
        s[tid] += t;
        __syncthreads();
    }
    if (tid < NBLK_SCAN) g_boff[tid] = s[tid] - g_bsum[tid];
}

__global__ void scan3_kernel() {
    int i = blockIdx.x * blockDim.x + threadIdx.x;
    if (i >= N_NODES) return;
    g_start[i + 1] = g_incl[i] + g_boff[i >> 8];
    g_cursor[i] = 0;
    if (i == 0) g_start[0] = 0;
}

__global__ void fill_kernel(const int* __restrict__ ei,
                            const int* __restrict__ ea) {
    int e = blockIdx.x * blockDim.x + threadIdx.x;
    if (e >= N_EDGES) return;
    int row = ei[e];
    int col = ei[N_EDGES + e];
    int attr = ea[2 * e] * 3 + ea[2 * e + 1];  // 0..8
    int pos = g_start[col] + atomicAdd(&g_cursor[col], 1);
    g_csr[pos] = row | (attr << 16);
}

// ---------------- 3xBF16 tensor-core GEMM (m16n8k16) with fused BN+ReLU ------
#define MMA_BF16(cc, A0, A1, A2, A3, B0, B1)                                   \
    asm volatile(                                                              \
        "mma.sync.aligned.m16n8k16.row.col.f32.bf16.bf16.f32 "                 \
        "{%0,%1,%2,%3},{%4,%5,%6,%7},{%8,%9},{%0,%1,%2,%3};"                   \
        : "+f"(cc[0]), "+f"(cc[1]), "+f"(cc[2]), "+f"(cc[3])                   \
        : "r"(A0), "r"(A1), "r"(A2), "r"(A3), "r"(B0), "r"(B1));

#define NKT 19  // ceil(300/16)

__device__ __forceinline__ unsigned bfus(__nv_bfloat16 b) {
    return (unsigned)__bfloat16_as_ushort(b);
}

__global__ __launch_bounds__(256)
void gemm_layer_tc(const float* __restrict__ Wl,   // [DIM, DIM] row-major
                   const float* __restrict__ src,  // g_h (l=0) or g_agg
                   int apply_bn) {
    // [buf][k_pair][m/n]; bank = (8*kp + m) mod 32 -> conflict-free loads
    __shared__ __align__(16) unsigned Ah[2][8][136], Al[2][8][136];
    __shared__ __align__(16) unsigned Bh[2][8][72],  Bl[2][8][72];

    const int tid = threadIdx.x;
    const int lane = tid & 31;
    const int warp = tid >> 5;
    const int g = lane >> 2;      // 0..7
    const int tg = lane & 3;      // 0..3
    const int wm = warp >> 1;     // 0..3 (m)
    const int wn = warp & 1;      // 0..1 (n)
    const int m0 = blockIdx.y * 128;
    const int n0 = blockIdx.x * 64;

    float c[2][4][4];
#pragma unroll
    for (int im = 0; im < 2; im++)
#pragma unroll
        for (int in = 0; in < 4; in++)
#pragma unroll
            for (int j = 0; j < 4; j++) c[im][in][j] = 0.f;

    // A loader: thread owns row m = tid&127, k-half (8 floats) = tid>>7
    const int a_m = tid & 127;
    const int a_kh = tid >> 7;         // 0 or 1
    const int gm = m0 + a_m;
    // B loader: thread owns k-pair kp = tid>>5 (0..7), cols n, n+1
    const int b_kp = tid >> 5;
    const int b_n = (tid & 31) * 2;    // 0..62

    float ar[8], br[4];

    auto loadA = [&](int kt) {
        int gk = kt * 16 + a_kh * 8;
        if (gm < N_NODES && gk + 7 < DIM) {
            const float4 v0 = *(const float4*)&src[gm * DIM + gk];
            const float4 v1 = *(const float4*)&src[gm * DIM + gk + 4];
            ar[0] = v0.x; ar[1] = v0.y; ar[2] = v0.z; ar[3] = v0.w;
            ar[4] = v1.x; ar[5] = v1.y; ar[6] = v1.z; ar[7] = v1.w;
            if (apply_bn) {
                const float4 s0 = *(const float4*)&g_coef[gk];
                const float4 s1 = *(const float4*)&g_coef[gk + 4];
                const float4 t0 = *(const float4*)&g_coef[DIM + gk];
                const float4 t1 = *(const float4*)&g_coef[DIM + gk + 4];
                ar[0] = fmaxf(ar[0] * s0.x + t0.x, 0.f);
                ar[1] = fmaxf(ar[1] * s0.y + t0.y, 0.f);
                ar[2] = fmaxf(ar[2] * s0.z + t0.z, 0.f);
                ar[3] = fmaxf(ar[3] * s0.w + t0.w, 0.f);
                ar[4] = fmaxf(ar[4] * s1.x + t1.x, 0.f);
                ar[5] = fmaxf(ar[5] * s1.y + t1.y, 0.f);
                ar[6] = fmaxf(ar[6] * s1.z + t1.z, 0.f);
                ar[7] = fmaxf(ar[7] * s1.w + t1.w, 0.f);
            }
        } else {
#pragma unroll
            for (int j = 0; j < 8; j++) {
                int k = gk + j;
                float v = (gm < N_NODES && k < DIM) ? src[gm * DIM + k] : 0.f;
                if (apply_bn && k < DIM)
                    v = fmaxf(v * g_coef[k] + g_coef[DIM + k], 0.f);
                ar[j] = v;
            }
        }
    };
    auto loadB = [&](int kt) {
        int r0 = kt * 16 + 2 * b_kp;
        int gn = n0 + b_n;
        if (r0 + 1 < DIM && gn + 1 < DIM) {
            const float2 v0 = *(const float2*)&Wl[r0 * DIM + gn];
            const float2 v1 = *(const float2*)&Wl[(r0 + 1) * DIM + gn];
            br[0] = v0.x; br[1] = v1.x;  // col gn, k-pair
            br[2] = v0.y; br[3] = v1.y;  // col gn+1
        } else {
            br[0] = (r0 < DIM && gn < DIM) ? Wl[r0 * DIM + gn] : 0.f;
            br[1] = (r0 + 1 < DIM && gn < DIM) ? Wl[(r0 + 1) * DIM + gn] : 0.f;
            br[2] = (r0 < DIM && gn + 1 < DIM) ? Wl[r0 * DIM + gn + 1] : 0.f;
            br[3] = (r0 + 1 < DIM && gn + 1 < DIM) ? Wl[(r0 + 1) * DIM + gn + 1]
                                                   : 0.f;
        }
    };
    auto stage = [&](int buf) {
#pragma unroll
        for (int p = 0; p < 4; p++) {
            float v0 = ar[2 * p], v1 = ar[2 * p + 1];
            __nv_bfloat16 h0 = __float2bfloat16_rn(v0);
            __nv_bfloat16 h1 = __float2bfloat16_rn(v1);
            Ah[buf][a_kh * 4 + p][a_m] = bfus(h0) | (bfus(h1) << 16);
            __nv_bfloat16 l0 = __float2bfloat16_rn(v0 - __bfloat162float(h0));
            __nv_bfloat16 l1 = __float2bfloat16_rn(v1 - __bfloat162float(h1));
            Al[buf][a_kh * 4 + p][a_m] = bfus(l0) | (bfus(l1) << 16);
        }
        {
            __nv_bfloat16 h00 = __float2bfloat16_rn(br[0]);
            __nv_bfloat16 h10 = __float2bfloat16_rn(br[1]);
            __nv_bfloat16 h01 = __float2bfloat16_rn(br[2]);
            __nv_bfloat16 h11 = __float2bfloat16_rn(br[3]);
            uint2 hv = make_uint2(bfus(h00) | (bfus(h10) << 16),
                                  bfus(h01) | (bfus(h11) << 16));
            *(uint2*)&Bh[buf][b_kp][b_n] = hv;
            __nv_bfloat16 l00 = __float2bfloat16_rn(br[0] - __bfloat162float(h00));
            __nv_bfloat16 l10 = __float2bfloat16_rn(br[1] - __bfloat162float(h10));
            __nv_bfloat16 l01 = __float2bfloat16_rn(br[2] - __bfloat162float(h01));
            __nv_bfloat16 l11 = __float2bfloat16_rn(br[3] - __bfloat162float(h11));
            uint2 lv = make_uint2(bfus(l00) | (bfus(l10) << 16),
                                  bfus(l01) | (bfus(l11) << 16));
            *(uint2*)&Bl[buf][b_kp][b_n] = lv;
        }
    };

    loadA(0); loadB(0); stage(0);
    __syncthreads();

#pragma unroll 1
    for (int kt = 0; kt < NKT; kt++) {
        const int buf = kt & 1;
        if (kt < NKT - 1) { loadA(kt + 1); loadB(kt + 1); }

        {
            unsigned ah0[2], ah1[2], ah2[2], ah3[2];
            unsigned al0[2], al1[2], al2[2], al3[2];
#pragma unroll
            for (int im = 0; im < 2; im++) {
                int mo = wm * 32 + im * 16;
                ah0[im] = Ah[buf][tg][mo + g];
                ah1[im] = Ah[buf][tg][mo + g + 8];
                ah2[im] = Ah[buf][tg + 4][mo + g];
                ah3[im] = Ah[buf][tg + 4][mo + g + 8];
                al0[im] = Al[buf][tg][mo + g];
                al1[im] = Al[buf][tg][mo + g + 8];
                al2[im] = Al[buf][tg + 4][mo + g];
                al3[im] = Al[buf][tg + 4][mo + g + 8];
            }
            unsigned bh0[4], bh1[4], bl0[4], bl1[4];
#pragma unroll
            for (int in = 0; in < 4; in++) {
                int no = wn * 32 + in * 8;
                bh0[in] = Bh[buf][tg][no + g];
                bh1[in] = Bh[buf][tg + 4][no + g];
                bl0[in] = Bl[buf][tg][no + g];
                bl1[in] = Bl[buf][tg + 4][no + g];
            }
#pragma unroll
            for (int im = 0; im < 2; im++)
#pragma unroll
                for (int in = 0; in < 4; in++) {
                    MMA_BF16(c[im][in], al0[im], al1[im], al2[im], al3[im],
                             bh0[in], bh1[in]);
                    MMA_BF16(c[im][in], ah0[im], ah1[im], ah2[im], ah3[im],
                             bl0[in], bl1[in]);
                    MMA_BF16(c[im][in], ah0[im], ah1[im], ah2[im], ah3[im],
                             bh0[in], bh1[in]);
                }
        }

        if (kt < NKT - 1) stage(buf ^ 1);
        __syncthreads();
    }

    // ---- epilogue: write g_hw ----
#pragma unroll
    for (int in = 0; in < 4; in++) {
        int ncol = n0 + wn * 32 + in * 8 + 2 * tg;
        if (ncol >= DIM) continue;
#pragma unroll
        for (int im = 0; im < 2; im++) {
            int r0 = m0 + wm * 32 + im * 16 + g;
            if (r0 < N_NODES)
                *(float2*)&g_hw[r0 * DIM + ncol] =
                    make_float2(c[im][in][0], c[im][in][1]);
            int r1 = r0 + 8;
            if (r1 < N_NODES)
                *(float2*)&g_hw[r1 * DIM + ncol] =
                    make_float2(c[im][in][2], c[im][in][3]);
        }
    }
}

// ---------------- CSR aggregation --------------------------------------------
__global__ __launch_bounds__(128)
void agg_kernel(const float* __restrict__ bl,
                const float* __restrict__ e1,
                const float* __restrict__ e2,
                int l) {
    __shared__ float s_em[9];
    __shared__ int s_pk[128];
    const int n = blockIdx.x;
    const int tid = threadIdx.x;
    if (tid < 9) s_em[tid] = e1[l * 5 + tid / 3] + e2[l * 3 + tid % 3];
    const float selfE = e1[l * 5 + 4] + e2[l * 3 + 0];
    __syncthreads();
    const int start = g_start[n], end = g_start[n + 1];
    const int d0 = tid, d1 = tid + 128, d2 = tid + 256;
    float a0 = 0.f, a1 = 0.f, a2 = 0.f;
    for (int base = start; base < end; base += 128) {
        int idx = base + tid;
        if (idx < end) s_pk[tid] = g_csr[idx];
        __syncthreads();
        int cnt = min(128, end - base);
#pragma unroll 4
        for (int i = 0; i < cnt; i++) {
            int pk = s_pk[i];
            const float* p = g_hw + (pk & 0xFFFF) * DIM;
            float em = s_em[pk >> 16];
            a0 += p[d0] + em;
            a1 += p[d1] + em;
            if (d2 < DIM) a2 += p[d2] + em;
        }
        __syncthreads();
    }
    const float* hp = g_hw + n * DIM;
    float* op = g_agg + n * DIM;
    op[d0] = a0 + hp[d0] + bl[d0] + selfE;
    op[d1] = a1 + hp[d1] + bl[d1] + selfE;
    if (d2 < DIM) op[d2] = a2 + hp[d2] + bl[d2] + selfE;
}

// ---------------- batch norm stats + coefficients ----------------------------
#define STAT_ROWS 50
__global__ void stats_kernel(int l) {
    int tid = threadIdx.x;            // 128
    int r0 = blockIdx.x * STAT_ROWS;
    float* st = &g_stats[l * 2 * DIM];
    int c0 = tid, c1 = tid + 128, c2 = tid + 256;
    float s0 = 0, q0 = 0, s1 = 0, q1 = 0, s2 = 0, q2 = 0;
    int rend = r0 + STAT_ROWS;
    if (rend > N_NODES) rend = N_NODES;
    for (int r = r0; r < rend; r++) {
        const float* p = &g_agg[(long)r * DIM];
        float v0 = p[c0]; s0 += v0; q0 += v0 * v0;
        float v1 = p[c1]; s1 += v1; q1 += v1 * v1;
        if (c2 < DIM) { float v2 = p[c2]; s2 += v2; q2 += v2 * v2; }
    }
    atomicAdd(&st[c0], s0);
    atomicAdd(&st[DIM + c0], q0);
    atomicAdd(&st[c1], s1);
    atomicAdd(&st[DIM + c1], q1);
    if (c2 < DIM) {
        atomicAdd(&st[c2], s2);
        atomicAdd(&st[DIM + c2], q2);
    }
}

__global__ void coef_kernel(const float* __restrict__ gamma,
                            const float* __restrict__ beta, int l) {
    int d = blockIdx.x * blockDim.x + threadIdx.x;
    if (d >= DIM) return;
    const float* st = &g_stats[l * 2 * DIM];
    const float inv_n = 1.0f / (float)N_NODES;
    float mu = st[d] * inv_n;
    float var = st[DIM + d] * inv_n - mu * mu;
    float s = rsqrtf(var + EPS) * gamma[l * DIM + d];
    g_coef[d] = s;
    g_coef[DIM + d] = beta[l * DIM + d] - mu * s;
}

// ---------------- pool (applies final BN; batch sorted -> segments) ----------
__global__ void gbound_kernel(const int* __restrict__ batch) {
    int g = blockIdx.x * blockDim.x + threadIdx.x;
    if (g > N_GRAPHS) return;
    int lo = 0, hi = N_NODES;
    while (lo < hi) {
        int mid = (lo + hi) >> 1;
        if (batch[mid] < g) lo = mid + 1; else hi = mid;
    }
    g_gstart[g] = lo;
}

__global__ __launch_bounds__(128)
void pool_kernel() {
    const int g = blockIdx.x;
    const int tid = threadIdx.x;
    const int gs = g_gstart[g], ge = g_gstart[g + 1];
    const int d0 = tid, d1 = tid + 128, d2 = tid + 256;
    float a0 = 0.f, a1 = 0.f, a2 = 0.f;
#pragma unroll 2
    for (int r = gs; r < ge; r++) {
        const float* p = g_agg + r * DIM;
        a0 += p[d0];
        a1 += p[d1];
        if (d2 < DIM) a2 += p[d2];
    }
    float inv = 1.0f / fmaxf((float)(ge - gs), 1.0f);
    float* op = g_hg + g * DIM;
    op[d0] = (a0 * inv) * g_coef[d0] + g_coef[DIM + d0];
    op[d1] = (a1 * inv) * g_coef[d1] + g_coef[DIM + d1];
    if (d2 < DIM) op[d2] = (a2 * inv) * g_coef[d2] + g_coef[DIM + d2];
}

// ---------------- head MLPs --------------------------------------------------
__global__ void gemm_feat(const float* __restrict__ fw,
                          const float* __restrict__ fb,
                          float* __restrict__ hfeat) {
    __shared__ float sh[DIM];
    int g = blockIdx.x;
    int t = threadIdx.x;  // 256
    for (int k = t; k < DIM; k += FEAT) sh[k] = g_hg[g * DIM + k];
    __syncthreads();
    float acc = fb[t];
    for (int k = 0; k < DIM; k++) acc += sh[k] * fw[k * FEAT + t];
    hfeat[g * FEAT + t] = acc;
}

__global__ void gemm_mlp1(const float* __restrict__ hfeat,
                          const float* __restrict__ w1,
                          const float* __restrict__ b1) {
    __shared__ float sh[FEAT];
    int g = blockIdx.x;
    int t = threadIdx.x;  // 256
    sh[t] = hfeat[g * FEAT + t];
    __syncthreads();
    float acc = b1[t];
    for (int k = 0; k < FEAT; k++) acc += sh[k] * w1[k * FEAT + t];
    g_hid[g * FEAT + t] = fmaxf(acc, 0.f);
}

__global__ void gemm_mlp2(const float* __restrict__ w2,
                          const float* __restrict__ b2,
                          float* __restrict__ out) {
    __shared__ float sh[FEAT];
    int g = blockIdx.x;
    int t = threadIdx.x;  // 128
    sh[t] = g_hid[g * FEAT + t];
    sh[t + 128] = g_hid[g * FEAT + t + 128];
    __syncthreads();
    float acc = b2[t];
    for (int k = 0; k < FEAT; k++) acc += sh[k] * w2[k * 128 + t];
    out[g * 128 + t] = acc;
}

// ---------------- launch -----------------------------------------------------
extern "C" void kernel_launch(void* const* d_in, const int* in_sizes, int n_in,
                              void* d_out, int out_size) {
    const int*   x     = (const int*)d_in[0];
    const int*   ei    = (const int*)d_in[1];
    const int*   ea    = (const int*)d_in[2];
    const int*   batch = (const int*)d_in[3];
    const float* emb1  = (const float*)d_in[4];
    const float* emb2  = (const float*)d_in[5];
    const float* W     = (const float*)d_in[6];
    const float* b     = (const float*)d_in[7];
    const float* e1    = (const float*)d_in[8];
    const float* e2    = (const float*)d_in[9];
    const float* gamma = (const float*)d_in[10];
    const float* beta  = (const float*)d_in[11];
    const float* fw    = (const float*)d_in[12];
    const float* fb    = (const float*)d_in[13];
    const float* w1    = (const float*)d_in[14];
    const float* b1    = (const float*)d_in[15];
    const float* w2    = (const float*)d_in[16];
    const float* b2    = (const float*)d_in[17];

    float* hfeat_out = (float*)d_out;
    float* final_out = (float*)d_out + N_GRAPHS * FEAT;

    float* d_h;   cudaGetSymbolAddress((void**)&d_h, g_h);
    float* d_agg; cudaGetSymbolAddress((void**)&d_agg, g_agg);

    dim3 ggrid((DIM + 63) / 64, (N_NODES + 127) / 128);

    // Launch order puts gemm_layer_tc at position #4 for ncu attribution.
    embed_kernel<<<(N_NODES * DIM + 255) / 256, 256>>>(x, emb1, emb2);  // 1
    hist_kernel<<<(N_EDGES + 255) / 256, 256>>>(ei);                    // 2
    scan1_kernel<<<NBLK_SCAN, 256>>>();                                 // 3
    gemm_layer_tc<<<ggrid, 256>>>(W, d_h, 0);                           // 4 (l=0)
    scan2_kernel<<<1, 256>>>();                                         // 5
    scan3_kernel<<<(N_NODES + 255) / 256, 256>>>();                     // 6
    fill_kernel<<<(N_EDGES + 255) / 256, 256>>>(ei, ea);                // 7

    for (int l = 0; l < N_LAYERS; l++) {
        if (l > 0)
            gemm_layer_tc<<<ggrid, 256>>>(W + (long)l * DIM * DIM, d_agg, 1);
        agg_kernel<<<N_NODES, 128>>>(b + l * DIM, e1, e2, l);
        stats_kernel<<<N_NODES / STAT_ROWS, 128>>>(l);
        coef_kernel<<<2, 256>>>(gamma, beta, l);
    }

    gbound_kernel<<<(N_GRAPHS + 256) / 256, 256>>>(batch);
    pool_kernel<<<N_GRAPHS, 128>>>();

    gemm_feat<<<N_GRAPHS, FEAT>>>(fw, fb, hfeat_out);
    gemm_mlp1<<<N_GRAPHS, FEAT>>>(hfeat_out, w1, b1);
    gemm_mlp2<<<N_GRAPHS, 128>>>(w2, b2, final_out);
}

// round 8
// speedup vs baseline: 1.4758x; 1.0792x over previous
#include <cuda_runtime.h>
#include <cuda_fp16.h>
#include <cuda_bf16.h>

#define N_NODES 50000
#define N_EDGES 800000
#define N_GRAPHS 1024
#define DIM 300
#define N_LAYERS 5
#define FEAT 256
#define EPS 1e-5f
#define NBLK_SCAN ((N_NODES + 255) / 256)   // 196

// ---------------- scratch (static device globals; no allocation) -------------
__device__ float  g_h[N_NODES * DIM];     // embed output (layer-0 input)
__device__ __half g_hwh[N_NODES * DIM];   // h @ W[l] in fp16 (30 MB)
__device__ float  g_agg[N_NODES * DIM];   // pre-BN accumulation
__device__ float  g_stats[N_LAYERS * 2 * DIM];
__device__ float  g_coef[2 * DIM];        // current layer BN scale/shift
__device__ float  g_emsum[N_LAYERS * N_NODES];  // per-node edge-emb sums
__device__ float  g_hg[N_GRAPHS * DIM];
__device__ float  g_hid[N_GRAPHS * FEAT];
// CSR build
__device__ int g_deg[N_NODES];
__device__ int g_incl[N_NODES];
__device__ int g_bsum[NBLK_SCAN];
__device__ int g_boff[NBLK_SCAN];
__device__ int g_cursor[N_NODES];
__device__ int g_start[N_NODES + 1];
__device__ int g_csr[N_EDGES];           // row | (attr<<16)
__device__ int g_gstart[N_GRAPHS + 1];

// ---------------- node embedding + zero deg/stats ----------------------------
__global__ void embed_kernel(const int* __restrict__ x,
                             const float* __restrict__ emb1,
                             const float* __restrict__ emb2) {
    int i = blockIdx.x * blockDim.x + threadIdx.x;
    if (i < N_LAYERS * 2 * DIM) g_stats[i] = 0.f;
    if (i < N_NODES) g_deg[i] = 0;
    if (i >= N_NODES * DIM) return;
    int n = i / DIM, d = i - n * DIM;
    int a = x[2 * n], c = x[2 * n + 1];
    g_h[i] = emb1[a * DIM + d] + emb2[c * DIM + d];
}

// ---------------- CSR build ---------------------------------------------------
__global__ void hist_kernel(const int* __restrict__ ei) {
    int e = blockIdx.x * blockDim.x + threadIdx.x;
    if (e >= N_EDGES) return;
    atomicAdd(&g_deg[ei[N_EDGES + e]], 1);
}

__global__ void scan1_kernel() {
    __shared__ int s[256];
    int tid = threadIdx.x;
    int i = blockIdx.x * 256 + tid;
    int v = (i < N_NODES) ? g_deg[i] : 0;
    s[tid] = v;
    __syncthreads();
#pragma unroll
    for (int off = 1; off < 256; off <<= 1) {
        int t = (tid >= off) ? s[tid - off] : 0;
        __syncthreads();
        s[tid] += t;
        __syncthreads();
    }
    if (i < N_NODES) g_incl[i] = s[tid];
    if (tid == 255) g_bsum[blockIdx.x] = s[255];
}

__global__ void scan2_kernel() {
    __shared__ int s[256];
    int tid = threadIdx.x;
    s[tid] = (tid < NBLK_SCAN) ? g_bsum[tid] : 0;
    __syncthreads();
#pragma unroll
    for (int off = 1; off < 256; off <<= 1) {
        int t = (tid >= off) ? s[tid - off] : 0;
        __syncthreads();
        s[tid] += t;
        __syncthreads();
    }
    if (tid < NBLK_SCAN) g_boff[tid] = s[tid] - g_bsum[tid];
}

__global__ void scan3_kernel() {
    int i = blockIdx.x * blockDim.x + threadIdx.x;
    if (i >= N_NODES) return;
    g_start[i + 1] = g_incl[i] + g_boff[i >> 8];
    g_cursor[i] = 0;
    if (i == 0) g_start[0] = 0;
}

__global__ void fill_kernel(const int* __restrict__ ei,
                            const int* __restrict__ ea) {
    int e = blockIdx.x * blockDim.x + threadIdx.x;
    if (e >= N_EDGES) return;
    int row = ei[e];
    int col = ei[N_EDGES + e];
    int attr = ea[2 * e] * 3 + ea[2 * e + 1];  // 0..8
    int pos = g_start[col] + atomicAdd(&g_cursor[col], 1);
    g_csr[pos] = row | (attr << 16);
}

// per-node sum of scalar edge embeddings, all layers at once
__global__ void emsum_kernel(const float* __restrict__ e1,
                             const float* __restrict__ e2) {
    __shared__ float tab[N_LAYERS][9];
    int tid = threadIdx.x;
    if (tid < N_LAYERS * 9) {
        int l = tid / 9, a = tid % 9;
        tab[l][a] = e1[l * 5 + a / 3] + e2[l * 3 + a % 3];
    }
    __syncthreads();
    int n = blockIdx.x * blockDim.x + tid;
    if (n >= N_NODES) return;
    float s[N_LAYERS] = {0.f, 0.f, 0.f, 0.f, 0.f};
    int e0 = g_start[n], e1i = g_start[n + 1];
    for (int e = e0; e < e1i; e++) {
        int a = g_csr[e] >> 16;
#pragma unroll
        for (int l = 0; l < N_LAYERS; l++) s[l] += tab[l][a];
    }
#pragma unroll
    for (int l = 0; l < N_LAYERS; l++) g_emsum[l * N_NODES + n] = s[l];
}

// ---------------- 3xBF16 tensor-core GEMM (m16n8k16) with fused BN+ReLU ------
#define MMA_BF16(cc, A0, A1, A2, A3, B0, B1)                                   \
    asm volatile(                                                              \
        "mma.sync.aligned.m16n8k16.row.col.f32.bf16.bf16.f32 "                 \
        "{%0,%1,%2,%3},{%4,%5,%6,%7},{%8,%9},{%0,%1,%2,%3};"                   \
        : "+f"(cc[0]), "+f"(cc[1]), "+f"(cc[2]), "+f"(cc[3])                   \
        : "r"(A0), "r"(A1), "r"(A2), "r"(A3), "r"(B0), "r"(B1));

#define NKT 19  // ceil(300/16)

__device__ __forceinline__ unsigned bfus(__nv_bfloat16 b) {
    return (unsigned)__bfloat16_as_ushort(b);
}

__global__ __launch_bounds__(256)
void gemm_layer_tc(const float* __restrict__ Wl,   // [DIM, DIM] row-major
                   const float* __restrict__ src,  // g_h (l=0) or g_agg
                   int apply_bn) {
    // [buf][k_pair][m/n]; bank = (8*kp + m) mod 32 -> conflict-free loads
    __shared__ __align__(16) unsigned Ah[2][8][136], Al[2][8][136];
    __shared__ __align__(16) unsigned Bh[2][8][72],  Bl[2][8][72];

    const int tid = threadIdx.x;
    const int lane = tid & 31;
    const int warp = tid >> 5;
    const int g = lane >> 2;      // 0..7
    const int tg = lane & 3;      // 0..3
    const int wm = warp >> 1;     // 0..3 (m)
    const int wn = warp & 1;      // 0..1 (n)
    const int m0 = blockIdx.y * 128;
    const int n0 = blockIdx.x * 64;

    float c[2][4][4];
#pragma unroll
    for (int im = 0; im < 2; im++)
#pragma unroll
        for (int in = 0; in < 4; in++)
#pragma unroll
            for (int j = 0; j < 4; j++) c[im][in][j] = 0.f;

    const int a_m = tid & 127;
    const int a_kh = tid >> 7;         // 0 or 1
    const int gm = m0 + a_m;
    const int b_kp = tid >> 5;
    const int b_n = (tid & 31) * 2;    // 0..62

    float ar[8], br[4];

    auto loadA = [&](int kt) {
        int gk = kt * 16 + a_kh * 8;
        if (gm < N_NODES && gk + 7 < DIM) {
            const float4 v0 = *(const float4*)&src[gm * DIM + gk];
            const float4 v1 = *(const float4*)&src[gm * DIM + gk + 4];
            ar[0] = v0.x; ar[1] = v0.y; ar[2] = v0.z; ar[3] = v0.w;
            ar[4] = v1.x; ar[5] = v1.y; ar[6] = v1.z; ar[7] = v1.w;
            if (apply_bn) {
                const float4 s0 = *(const float4*)&g_coef[gk];
                const float4 s1 = *(const float4*)&g_coef[gk + 4];
                const float4 t0 = *(const float4*)&g_coef[DIM + gk];
                const float4 t1 = *(const float4*)&g_coef[DIM + gk + 4];
                ar[0] = fmaxf(ar[0] * s0.x + t0.x, 0.f);
                ar[1] = fmaxf(ar[1] * s0.y + t0.y, 0.f);
                ar[2] = fmaxf(ar[2] * s0.z + t0.z, 0.f);
                ar[3] = fmaxf(ar[3] * s0.w + t0.w, 0.f);
                ar[4] = fmaxf(ar[4] * s1.x + t1.x, 0.f);
                ar[5] = fmaxf(ar[5] * s1.y + t1.y, 0.f);
                ar[6] = fmaxf(ar[6] * s1.z + t1.z, 0.f);
                ar[7] = fmaxf(ar[7] * s1.w + t1.w, 0.f);
            }
        } else {
#pragma unroll
            for (int j = 0; j < 8; j++) {
                int k = gk + j;
                float v = (gm < N_NODES && k < DIM) ? src[gm * DIM + k] : 0.f;
                if (apply_bn && k < DIM)
                    v = fmaxf(v * g_coef[k] + g_coef[DIM + k], 0.f);
                ar[j] = v;
            }
        }
    };
    auto loadB = [&](int kt) {
        int r0 = kt * 16 + 2 * b_kp;
        int gn = n0 + b_n;
        if (r0 + 1 < DIM && gn + 1 < DIM) {
            const float2 v0 = *(const float2*)&Wl[r0 * DIM + gn];
            const float2 v1 = *(const float2*)&Wl[(r0 + 1) * DIM + gn];
            br[0] = v0.x; br[1] = v1.x;
            br[2] = v0.y; br[3] = v1.y;
        } else {
            br[0] = (r0 < DIM && gn < DIM) ? Wl[r0 * DIM + gn] : 0.f;
            br[1] = (r0 + 1 < DIM && gn < DIM) ? Wl[(r0 + 1) * DIM + gn] : 0.f;
            br[2] = (r0 < DIM && gn + 1 < DIM) ? Wl[r0 * DIM + gn + 1] : 0.f;
            br[3] = (r0 + 1 < DIM && gn + 1 < DIM) ? Wl[(r0 + 1) * DIM + gn + 1]
                                                   : 0.f;
        }
    };
    auto stage = [&](int buf) {
#pragma unroll
        for (int p = 0; p < 4; p++) {
            float v0 = ar[2 * p], v1 = ar[2 * p + 1];
            __nv_bfloat16 h0 = __float2bfloat16_rn(v0);
            __nv_bfloat16 h1 = __float2bfloat16_rn(v1);
            Ah[buf][a_kh * 4 + p][a_m] = bfus(h0) | (bfus(h1) << 16);
            __nv_bfloat16 l0 = __float2bfloat16_rn(v0 - __bfloat162float(h0));
            __nv_bfloat16 l1 = __float2bfloat16_rn(v1 - __bfloat162float(h1));
            Al[buf][a_kh * 4 + p][a_m] = bfus(l0) | (bfus(l1) << 16);
        }
        {
            __nv_bfloat16 h00 = __float2bfloat16_rn(br[0]);
            __nv_bfloat16 h10 = __float2bfloat16_rn(br[1]);
            __nv_bfloat16 h01 = __float2bfloat16_rn(br[2]);
            __nv_bfloat16 h11 = __float2bfloat16_rn(br[3]);
            uint2 hv = make_uint2(bfus(h00) | (bfus(h10) << 16),
                                  bfus(h01) | (bfus(h11) << 16));
            *(uint2*)&Bh[buf][b_kp][b_n] = hv;
            __nv_bfloat16 l00 = __float2bfloat16_rn(br[0] - __bfloat162float(h00));
            __nv_bfloat16 l10 = __float2bfloat16_rn(br[1] - __bfloat162float(h10));
            __nv_bfloat16 l01 = __float2bfloat16_rn(br[2] - __bfloat162float(h01));
            __nv_bfloat16 l11 = __float2bfloat16_rn(br[3] - __bfloat162float(h11));
            uint2 lv = make_uint2(bfus(l00) | (bfus(l10) << 16),
                                  bfus(l01) | (bfus(l11) << 16));
            *(uint2*)&Bl[buf][b_kp][b_n] = lv;
        }
    };

    loadA(0); loadB(0); stage(0);
    __syncthreads();

#pragma unroll 1
    for (int kt = 0; kt < NKT; kt++) {
        const int buf = kt & 1;
        if (kt < NKT - 1) { loadA(kt + 1); loadB(kt + 1); }

        {
            unsigned ah0[2], ah1[2], ah2[2], ah3[2];
            unsigned al0[2], al1[2], al2[2], al3[2];
#pragma unroll
            for (int im = 0; im < 2; im++) {
                int mo = wm * 32 + im * 16;
                ah0[im] = Ah[buf][tg][mo + g];
                ah1[im] = Ah[buf][tg][mo + g + 8];
                ah2[im] = Ah[buf][tg + 4][mo + g];
                ah3[im] = Ah[buf][tg + 4][mo + g + 8];
                al0[im] = Al[buf][tg][mo + g];
                al1[im] = Al[buf][tg][mo + g + 8];
                al2[im] = Al[buf][tg + 4][mo + g];
                al3[im] = Al[buf][tg + 4][mo + g + 8];
            }
            unsigned bh0[4], bh1[4], bl0[4], bl1[4];
#pragma unroll
            for (int in = 0; in < 4; in++) {
                int no = wn * 32 + in * 8;
                bh0[in] = Bh[buf][tg][no + g];
                bh1[in] = Bh[buf][tg + 4][no + g];
                bl0[in] = Bl[buf][tg][no + g];
                bl1[in] = Bl[buf][tg + 4][no + g];
            }
#pragma unroll
            for (int im = 0; im < 2; im++)
#pragma unroll
                for (int in = 0; in < 4; in++) {
                    MMA_BF16(c[im][in], al0[im], al1[im], al2[im], al3[im],
                             bh0[in], bh1[in]);
                    MMA_BF16(c[im][in], ah0[im], ah1[im], ah2[im], ah3[im],
                             bl0[in], bl1[in]);
                    MMA_BF16(c[im][in], ah0[im], ah1[im], ah2[im], ah3[im],
                             bh0[in], bh1[in]);
                }
        }

        if (kt < NKT - 1) stage(buf ^ 1);
        __syncthreads();
    }

    // ---- epilogue: write g_hwh (fp16, half2 stores) ----
#pragma unroll
    for (int in = 0; in < 4; in++) {
        int ncol = n0 + wn * 32 + in * 8 + 2 * tg;
        if (ncol >= DIM) continue;
#pragma unroll
        for (int im = 0; im < 2; im++) {
            int r0 = m0 + wm * 32 + im * 16 + g;
            if (r0 < N_NODES)
                *(__half2*)&g_hwh[r0 * DIM + ncol] =
                    __floats2half2_rn(c[im][in][0], c[im][in][1]);
            int r1 = r0 + 8;
            if (r1 < N_NODES)
                *(__half2*)&g_hwh[r1 * DIM + ncol] =
                    __floats2half2_rn(c[im][in][2], c[im][in][3]);
        }
    }
}

// ---------------- CSR aggregation (fp16 gather, half2 lanes) ------------------
__global__ __launch_bounds__(160)
void agg_kernel(const float* __restrict__ bl,
                const float* __restrict__ e1,
                const float* __restrict__ e2,
                int l) {
    __shared__ int s_pk[160];
    const int n = blockIdx.x;
    const int tid = threadIdx.x;
    const int start = g_start[n], end = g_start[n + 1];
    const float selfE = e1[l * 5 + 4] + e2[l * 3 + 0];
    float ax = 0.f, ay = 0.f;
    for (int base = start; base < end; base += 160) {
        int idx = base + tid;
        if (idx < end) s_pk[tid] = g_csr[idx];
        __syncthreads();
        int cnt = min(160, end - base);
        if (tid < 150) {
#pragma unroll 4
            for (int i = 0; i < cnt; i++) {
                int row = s_pk[i] & 0xFFFF;
                float2 f = __half22float2(
                    *(const __half2*)&g_hwh[row * DIM + 2 * tid]);
                ax += f.x; ay += f.y;
            }
        }
        __syncthreads();
    }
    if (tid < 150) {
        float em = g_emsum[l * N_NODES + n] + selfE;
        float2 s = __half22float2(*(const __half2*)&g_hwh[n * DIM + 2 * tid]);
        float2 o;
        o.x = ax + s.x + bl[2 * tid] + em;
        o.y = ay + s.y + bl[2 * tid + 1] + em;
        *(float2*)&g_agg[n * DIM + 2 * tid] = o;
    }
}

// ---------------- batch norm stats + coefficients ----------------------------
#define STAT_ROWS 50
__global__ void stats_kernel(int l) {
    int tid = threadIdx.x;            // 128
    int r0 = blockIdx.x * STAT_ROWS;
    float* st = &g_stats[l * 2 * DIM];
    int c0 = tid, c1 = tid + 128, c2 = tid + 256;
    float s0 = 0, q0 = 0, s1 = 0, q1 = 0, s2 = 0, q2 = 0;
    int rend = r0 + STAT_ROWS;
    if (rend > N_NODES) rend = N_NODES;
#pragma unroll 4
    for (int r = r0; r < rend; r++) {
        const float* p = &g_agg[(long)r * DIM];
        float v0 = p[c0]; s0 += v0; q0 += v0 * v0;
        float v1 = p[c1]; s1 += v1; q1 += v1 * v1;
        if (c2 < DIM) { float v2 = p[c2]; s2 += v2; q2 += v2 * v2; }
    }
    atomicAdd(&st[c0], s0);
    atomicAdd(&st[DIM + c0], q0);
    atomicAdd(&st[c1], s1);
    atomicAdd(&st[DIM + c1], q1);
    if (c2 < DIM) {
        atomicAdd(&st[c2], s2);
        atomicAdd(&st[DIM + c2], q2);
    }
}

__global__ void coef_kernel(const float* __restrict__ gamma,
                            const float* __restrict__ beta, int l) {
    int d = blockIdx.x * blockDim.x + threadIdx.x;
    if (d >= DIM) return;
    const float* st = &g_stats[l * 2 * DIM];
    const float inv_n = 1.0f / (float)N_NODES;
    float mu = st[d] * inv_n;
    float var = st[DIM + d] * inv_n - mu * mu;
    float s = rsqrtf(var + EPS) * gamma[l * DIM + d];
    g_coef[d] = s;
    g_coef[DIM + d] = beta[l * DIM + d] - mu * s;
}

// ---------------- pool (applies final BN; batch sorted -> segments) ----------
__global__ void gbound_kernel(const int* __restrict__ batch) {
    int g = blockIdx.x * blockDim.x + threadIdx.x;
    if (g > N_GRAPHS) return;
    int lo = 0, hi = N_NODES;
    while (lo < hi) {
        int mid = (lo + hi) >> 1;
        if (batch[mid] < g) lo = mid + 1; else hi = mid;
    }
    g_gstart[g] = lo;
}

__global__ __launch_bounds__(128)
void pool_kernel() {
    const int g = blockIdx.x;
    const int tid = threadIdx.x;
    const int gs = g_gstart[g], ge = g_gstart[g + 1];
    const int d0 = tid, d1 = tid + 128, d2 = tid + 256;
    float a0 = 0.f, a1 = 0.f, a2 = 0.f;
#pragma unroll 2
    for (int r = gs; r < ge; r++) {
        const float* p = g_agg + r * DIM;
        a0 += p[d0];
        a1 += p[d1];
        if (d2 < DIM) a2 += p[d2];
    }
    float inv = 1.0f / fmaxf((float)(ge - gs), 1.0f);
    float* op = g_hg + g * DIM;
    op[d0] = (a0 * inv) * g_coef[d0] + g_coef[DIM + d0];
    op[d1] = (a1 * inv) * g_coef[d1] + g_coef[DIM + d1];
    if (d2 < DIM) op[d2] = (a2 * inv) * g_coef[d2] + g_coef[DIM + d2];
}

// ---------------- head MLPs --------------------------------------------------
__global__ void gemm_feat(const float* __restrict__ fw,
                          const float* __restrict__ fb,
                          float* __restrict__ hfeat) {
    __shared__ float sh[DIM];
    int g = blockIdx.x;
    int t = threadIdx.x;  // 256
    for (int k = t; k < DIM; k += FEAT) sh[k] = g_hg[g * DIM + k];
    __syncthreads();
    float acc = fb[t];
    for (int k = 0; k < DIM; k++) acc += sh[k] * fw[k * FEAT + t];
    hfeat[g * FEAT + t] = acc;
}

__global__ void gemm_mlp1(const float* __restrict__ hfeat,
                          const float* __restrict__ w1,
                          const float* __restrict__ b1) {
    __shared__ float sh[FEAT];
    int g = blockIdx.x;
    int t = threadIdx.x;  // 256
    sh[t] = hfeat[g * FEAT + t];
    __syncthreads();
    float acc = b1[t];
    for (int k = 0; k < FEAT; k++) acc += sh[k] * w1[k * FEAT + t];
    g_hid[g * FEAT + t] = fmaxf(acc, 0.f);
}

__global__ void gemm_mlp2(const float* __restrict__ w2,
                          const float* __restrict__ b2,
                          float* __restrict__ out) {
    __shared__ float sh[FEAT];
    int g = blockIdx.x;
    int t = threadIdx.x;  // 128
    sh[t] = g_hid[g * FEAT + t];
    sh[t + 128] = g_hid[g * FEAT + t + 128];
    __syncthreads();
    float acc = b2[t];
    for (int k = 0; k < FEAT; k++) acc += sh[k] * w2[k * 128 + t];
    out[g * 128 + t] = acc;
}

// ---------------- launch -----------------------------------------------------
extern "C" void kernel_launch(void* const* d_in, const int* in_sizes, int n_in,
                              void* d_out, int out_size) {
    const int*   x     = (const int*)d_in[0];
    const int*   ei    = (const int*)d_in[1];
    const int*   ea    = (const int*)d_in[2];
    const int*   batch = (const int*)d_in[3];
    const float* emb1  = (const float*)d_in[4];
    const float* emb2  = (const float*)d_in[5];
    const float* W     = (const float*)d_in[6];
    const float* b     = (const float*)d_in[7];
    const float* e1    = (const float*)d_in[8];
    const float* e2    = (const float*)d_in[9];
    const float* gamma = (const float*)d_in[10];
    const float* beta  = (const float*)d_in[11];
    const float* fw    = (const float*)d_in[12];
    const float* fb    = (const float*)d_in[13];
    const float* w1    = (const float*)d_in[14];
    const float* b1    = (const float*)d_in[15];
    const float* w2    = (const float*)d_in[16];
    const float* b2    = (const float*)d_in[17];

    float* hfeat_out = (float*)d_out;
    float* final_out = (float*)d_out + N_GRAPHS * FEAT;

    float* d_h;   cudaGetSymbolAddress((void**)&d_h, g_h);
    float* d_agg; cudaGetSymbolAddress((void**)&d_agg, g_agg);

    dim3 ggrid((DIM + 63) / 64, (N_NODES + 127) / 128);

    // Launch order puts gemm_layer_tc at position #4 for ncu attribution.
    embed_kernel<<<(N_NODES * DIM + 255) / 256, 256>>>(x, emb1, emb2);  // 1
    hist_kernel<<<(N_EDGES + 255) / 256, 256>>>(ei);                    // 2
    scan1_kernel<<<NBLK_SCAN, 256>>>();                                 // 3
    gemm_layer_tc<<<ggrid, 256>>>(W, d_h, 0);                           // 4 (l=0)
    scan2_kernel<<<1, 256>>>();                                         // 5
    scan3_kernel<<<(N_NODES + 255) / 256, 256>>>();                     // 6
    fill_kernel<<<(N_EDGES + 255) / 256, 256>>>(ei, ea);                // 7
    emsum_kernel<<<NBLK_SCAN, 256>>>(e1, e2);                           // 8

    for (int l = 0; l < N_LAYERS; l++) {
        if (l > 0)
            gemm_layer_tc<<<ggrid, 256>>>(W + (long)l * DIM * DIM, d_agg, 1);
        agg_kernel<<<N_NODES, 160>>>(b + l * DIM, e1, e2, l);
        stats_kernel<<<N_NODES / STAT_ROWS, 128>>>(l);
        coef_kernel<<<2, 256>>>(gamma, beta, l);
    }

    gbound_kernel<<<(N_GRAPHS + 256) / 256, 256>>>(batch);
    pool_kernel<<<N_GRAPHS, 128>>>();

    gemm_feat<<<N_GRAPHS, FEAT>>>(fw, fb, hfeat_out);
    gemm_mlp1<<<N_GRAPHS, FEAT>>>(hfeat_out, w1, b1);
    gemm_mlp2<<<N_GRAPHS, 128>>>(w2, b2, final_out);
}

// round 9
// speedup vs baseline: 1.5349x; 1.0400x over previous
#include <cuda_runtime.h>
#include <cuda_fp16.h>
#include <cuda_bf16.h>

#define N_NODES 50000
#define N_EDGES 800000
#define N_GRAPHS 1024
#define DIM 300
#define N_LAYERS 5
#define FEAT 256
#define EPS 1e-5f
#define NBLK_SCAN ((N_NODES + 255) / 256)   // 196

// ---------------- scratch (static device globals; no allocation) -------------
__device__ float  g_h[N_NODES * DIM];     // embed output (layer-0 input)
__device__ __half g_hwh[N_NODES * DIM];   // h @ W[l] in fp16 (30 MB)
__device__ float  g_agg[N_NODES * DIM];   // pre-BN accumulation
__device__ float  g_stats[N_LAYERS * 2 * DIM];
__device__ float  g_coef[2 * DIM];        // current layer BN scale/shift
__device__ float  g_emsum[N_LAYERS * N_NODES];  // per-node edge-emb sums
__device__ float  g_hg[N_GRAPHS * DIM];
__device__ float  g_hid[N_GRAPHS * FEAT];
// CSR build
__device__ int g_deg[N_NODES];
__device__ int g_incl[N_NODES];
__device__ int g_bsum[NBLK_SCAN];
__device__ int g_boff[NBLK_SCAN];
__device__ int g_cursor[N_NODES];
__device__ int g_start[N_NODES + 1];
__device__ int g_csr[N_EDGES];           // row | (attr<<16)
__device__ int g_gstart[N_GRAPHS + 1];

// ---------------- node embedding + zero deg/stats ----------------------------
__global__ void embed_kernel(const int* __restrict__ x,
                             const float* __restrict__ emb1,
                             const float* __restrict__ emb2) {
    int i = blockIdx.x * blockDim.x + threadIdx.x;
    if (i < N_LAYERS * 2 * DIM) g_stats[i] = 0.f;
    if (i < N_NODES) g_deg[i] = 0;
    if (i >= N_NODES * DIM) return;
    int n = i / DIM, d = i - n * DIM;
    int a = x[2 * n], c = x[2 * n + 1];
    g_h[i] = emb1[a * DIM + d] + emb2[c * DIM + d];
}

// ---------------- CSR build ---------------------------------------------------
__global__ void hist_kernel(const int* __restrict__ ei) {
    int e = blockIdx.x * blockDim.x + threadIdx.x;
    if (e >= N_EDGES) return;
    atomicAdd(&g_deg[ei[N_EDGES + e]], 1);
}

__global__ void scan1_kernel() {
    __shared__ int s[256];
    int tid = threadIdx.x;
    int i = blockIdx.x * 256 + tid;
    int v = (i < N_NODES) ? g_deg[i] : 0;
    s[tid] = v;
    __syncthreads();
#pragma unroll
    for (int off = 1; off < 256; off <<= 1) {
        int t = (tid >= off) ? s[tid - off] : 0;
        __syncthreads();
        s[tid] += t;
        __syncthreads();
    }
    if (i < N_NODES) g_incl[i] = s[tid];
    if (tid == 255) g_bsum[blockIdx.x] = s[255];
}

__global__ void scan2_kernel() {
    __shared__ int s[256];
    int tid = threadIdx.x;
    s[tid] = (tid < NBLK_SCAN) ? g_bsum[tid] : 0;
    __syncthreads();
#pragma unroll
    for (int off = 1; off < 256; off <<= 1) {
        int t = (tid >= off) ? s[tid - off] : 0;
        __syncthreads();
        s[tid] += t;
        __syncthreads();
    }
    if (tid < NBLK_SCAN) g_boff[tid] = s[tid] - g_bsum[tid];
}

__global__ void scan3_kernel() {
    int i = blockIdx.x * blockDim.x + threadIdx.x;
    if (i >= N_NODES) return;
    g_start[i + 1] = g_incl[i] + g_boff[i >> 8];
    g_cursor[i] = 0;
    if (i == 0) g_start[0] = 0;
}

__global__ void fill_kernel(const int* __restrict__ ei,
                            const int* __restrict__ ea) {
    int e = blockIdx.x * blockDim.x + threadIdx.x;
    if (e >= N_EDGES) return;
    int row = ei[e];
    int col = ei[N_EDGES + e];
    int attr = ea[2 * e] * 3 + ea[2 * e + 1];  // 0..8
    int pos = g_start[col] + atomicAdd(&g_cursor[col], 1);
    g_csr[pos] = row | (attr << 16);
}

// per-node sum of scalar edge embeddings, all layers at once
__global__ void emsum_kernel(const float* __restrict__ e1,
                             const float* __restrict__ e2) {
    __shared__ float tab[N_LAYERS][9];
    int tid = threadIdx.x;
    if (tid < N_LAYERS * 9) {
        int l = tid / 9, a = tid % 9;
        tab[l][a] = e1[l * 5 + a / 3] + e2[l * 3 + a % 3];
    }
    __syncthreads();
    int n = blockIdx.x * blockDim.x + tid;
    if (n >= N_NODES) return;
    float s[N_LAYERS] = {0.f, 0.f, 0.f, 0.f, 0.f};
    int e0 = g_start[n], e1i = g_start[n + 1];
    for (int e = e0; e < e1i; e++) {
        int a = g_csr[e] >> 16;
#pragma unroll
        for (int l = 0; l < N_LAYERS; l++) s[l] += tab[l][a];
    }
#pragma unroll
    for (int l = 0; l < N_LAYERS; l++) g_emsum[l * N_NODES + n] = s[l];
}

// ---------------- 3xBF16 tensor-core GEMM (ldmatrix + m16n8k16) --------------
#define MMA_BF16(cc, A0, A1, A2, A3, B0, B1)                                   \
    asm volatile(                                                              \
        "mma.sync.aligned.m16n8k16.row.col.f32.bf16.bf16.f32 "                 \
        "{%0,%1,%2,%3},{%4,%5,%6,%7},{%8,%9},{%0,%1,%2,%3};"                   \
        : "+f"(cc[0]), "+f"(cc[1]), "+f"(cc[2]), "+f"(cc[3])                   \
        : "r"(A0), "r"(A1), "r"(A2), "r"(A3), "r"(B0), "r"(B1));

__device__ __forceinline__ void ldsm_x4(unsigned& r0, unsigned& r1,
                                        unsigned& r2, unsigned& r3,
                                        unsigned addr) {
    asm volatile("ldmatrix.sync.aligned.m8n8.x4.shared.b16 {%0,%1,%2,%3}, [%4];"
                 : "=r"(r0), "=r"(r1), "=r"(r2), "=r"(r3) : "r"(addr));
}
__device__ __forceinline__ void ldsm_x4_t(unsigned& r0, unsigned& r1,
                                          unsigned& r2, unsigned& r3,
                                          unsigned addr) {
    asm volatile(
        "ldmatrix.sync.aligned.m8n8.x4.trans.shared.b16 {%0,%1,%2,%3}, [%4];"
        : "=r"(r0), "=r"(r1), "=r"(r2), "=r"(r3) : "r"(addr));
}

#define NKT 19  // ceil(300/16)
#define A_RS 24  // A row stride in bf16 (48 B: 3*16B -> group 3m mod 8, coprime)
#define B_RS 72  // B row stride in bf16 (144 B: 9*16B -> group k mod 8)

__device__ __forceinline__ unsigned bfus(__nv_bfloat16 b) {
    return (unsigned)__bfloat16_as_ushort(b);
}

__global__ __launch_bounds__(256)
void gemm_layer_tc(const float* __restrict__ Wl,   // [DIM, DIM] row-major
                   const float* __restrict__ src,  // g_h (l=0) or g_agg
                   int apply_bn) {
    __shared__ __align__(16) __nv_bfloat16 Ahi[2][128][A_RS], Alo[2][128][A_RS];
    __shared__ __align__(16) __nv_bfloat16 Bhi[2][16][B_RS],  Blo[2][16][B_RS];

    const int tid = threadIdx.x;
    const int lane = tid & 31;
    const int warp = tid >> 5;
    const int g = lane >> 2;      // 0..7
    const int tg = lane & 3;      // 0..3
    const int wm = warp >> 1;     // 0..3 (m)
    const int wn = warp & 1;      // 0..1 (n)
    const int m0 = blockIdx.y * 128;
    const int n0 = blockIdx.x * 64;

    float c[2][4][4];
#pragma unroll
    for (int im = 0; im < 2; im++)
#pragma unroll
        for (int in = 0; in < 4; in++)
#pragma unroll
            for (int j = 0; j < 4; j++) c[im][in][j] = 0.f;

    // A loader: row a_m = tid&127, k-half (8 floats) = tid>>7
    const int a_m = tid & 127;
    const int a_kh = tid >> 7;         // 0 or 1
    const int gm = m0 + a_m;
    // B loader: k-row = tid>>4 (0..15), 4 n-values at (tid&15)*4
    const int b_k = tid >> 4;
    const int b_nc = (tid & 15) * 4;

    float ar[8], br[4];

    auto loadA = [&](int kt) {
        int gk = kt * 16 + a_kh * 8;
        if (gm < N_NODES && gk + 7 < DIM) {
            const float4 v0 = *(const float4*)&src[gm * DIM + gk];
            const float4 v1 = *(const float4*)&src[gm * DIM + gk + 4];
            ar[0] = v0.x; ar[1] = v0.y; ar[2] = v0.z; ar[3] = v0.w;
            ar[4] = v1.x; ar[5] = v1.y; ar[6] = v1.z; ar[7] = v1.w;
            if (apply_bn) {
                const float4 s0 = *(const float4*)&g_coef[gk];
                const float4 s1 = *(const float4*)&g_coef[gk + 4];
                const float4 t0 = *(const float4*)&g_coef[DIM + gk];
                const float4 t1 = *(const float4*)&g_coef[DIM + gk + 4];
                ar[0] = fmaxf(ar[0] * s0.x + t0.x, 0.f);
                ar[1] = fmaxf(ar[1] * s0.y + t0.y, 0.f);
                ar[2] = fmaxf(ar[2] * s0.z + t0.z, 0.f);
                ar[3] = fmaxf(ar[3] * s0.w + t0.w, 0.f);
                ar[4] = fmaxf(ar[4] * s1.x + t1.x, 0.f);
                ar[5] = fmaxf(ar[5] * s1.y + t1.y, 0.f);
                ar[6] = fmaxf(ar[6] * s1.z + t1.z, 0.f);
                ar[7] = fmaxf(ar[7] * s1.w + t1.w, 0.f);
            }
        } else {
#pragma unroll
            for (int j = 0; j < 8; j++) {
                int k = gk + j;
                float v = (gm < N_NODES && k < DIM) ? src[gm * DIM + k] : 0.f;
                if (apply_bn && k < DIM)
                    v = fmaxf(v * g_coef[k] + g_coef[DIM + k], 0.f);
                ar[j] = v;
            }
        }
    };
    auto loadB = [&](int kt) {
        int r = kt * 16 + b_k;
        int gn = n0 + b_nc;
        if (r < DIM && gn + 3 < DIM) {
            const float4 v = *(const float4*)&Wl[r * DIM + gn];
            br[0] = v.x; br[1] = v.y; br[2] = v.z; br[3] = v.w;
        } else {
#pragma unroll
            for (int j = 0; j < 4; j++)
                br[j] = (r < DIM && gn + j < DIM) ? Wl[r * DIM + gn + j] : 0.f;
        }
    };
    auto stage = [&](int buf) {
        // A: 8 hi bf16 (16 B) + 8 lo bf16 as uint4 stores; row stride 48 B.
        unsigned h[4], l[4];
#pragma unroll
        for (int p = 0; p < 4; p++) {
            __nv_bfloat16 h0 = __float2bfloat16_rn(ar[2 * p]);
            __nv_bfloat16 h1 = __float2bfloat16_rn(ar[2 * p + 1]);
            h[p] = bfus(h0) | (bfus(h1) << 16);
            __nv_bfloat16 l0 =
                __float2bfloat16_rn(ar[2 * p] - __bfloat162float(h0));
            __nv_bfloat16 l1 =
                __float2bfloat16_rn(ar[2 * p + 1] - __bfloat162float(h1));
            l[p] = bfus(l0) | (bfus(l1) << 16);
        }
        *(uint4*)&Ahi[buf][a_m][a_kh * 8] = make_uint4(h[0], h[1], h[2], h[3]);
        *(uint4*)&Alo[buf][a_m][a_kh * 8] = make_uint4(l[0], l[1], l[2], l[3]);
        // B: 4 hi bf16 (8 B) + 4 lo as uint2 stores; row stride 144 B.
        __nv_bfloat16 bh0 = __float2bfloat16_rn(br[0]);
        __nv_bfloat16 bh1 = __float2bfloat16_rn(br[1]);
        __nv_bfloat16 bh2 = __float2bfloat16_rn(br[2]);
        __nv_bfloat16 bh3 = __float2bfloat16_rn(br[3]);
        *(uint2*)&Bhi[buf][b_k][b_nc] =
            make_uint2(bfus(bh0) | (bfus(bh1) << 16),
                       bfus(bh2) | (bfus(bh3) << 16));
        __nv_bfloat16 bl0 = __float2bfloat16_rn(br[0] - __bfloat162float(bh0));
        __nv_bfloat16 bl1 = __float2bfloat16_rn(br[1] - __bfloat162float(bh1));
        __nv_bfloat16 bl2 = __float2bfloat16_rn(br[2] - __bfloat162float(bh2));
        __nv_bfloat16 bl3 = __float2bfloat16_rn(br[3] - __bfloat162float(bh3));
        *(uint2*)&Blo[buf][b_k][b_nc] =
            make_uint2(bfus(bl0) | (bfus(bl1) << 16),
                       bfus(bl2) | (bfus(bl3) << 16));
    };

    // ldmatrix per-thread source offsets (element indices within a tile)
    // A (x4, non-trans): mat0 m0-7/k0-7, mat1 m8-15/k0-7, mat2 m0-7/k8-15,
    //                    mat3 m8-15/k8-15  -> rows a0..a3 of the MMA A frag.
    const int a_row = (lane & 15);          // + wm*32 + im*16
    const int a_chk = (lane >> 4) * 8;      // k offset 0 or 8
    // B (x4, trans) on k-major [k][n]: mat0 k0-7/n0-7 -> b0(ntile0),
    //   mat1 k8-15/n0-7 -> b1(ntile0), mat2/mat3 -> ntile1.
    const int b_row = ((lane >> 3) & 1) * 8 + (lane & 7);
    const int b_chk = (lane >> 4) * 8;      // n offset 0 or 8

    loadA(0); loadB(0); stage(0);
    __syncthreads();

#pragma unroll 1
    for (int kt = 0; kt < NKT; kt++) {
        const int buf = kt & 1;
        if (kt < NKT - 1) { loadA(kt + 1); loadB(kt + 1); }

        {
            unsigned ah[2][4], al[2][4];
#pragma unroll
            for (int im = 0; im < 2; im++) {
                int mrow = wm * 32 + im * 16 + a_row;
                unsigned ahh = (unsigned)__cvta_generic_to_shared(
                    &Ahi[buf][mrow][a_chk]);
                unsigned all_ = (unsigned)__cvta_generic_to_shared(
                    &Alo[buf][mrow][a_chk]);
                ldsm_x4(ah[im][0], ah[im][1], ah[im][2], ah[im][3], ahh);
                ldsm_x4(al[im][0], al[im][1], al[im][2], al[im][3], all_);
            }
            unsigned bh[4][2], bl[4][2];
#pragma unroll
            for (int pair = 0; pair < 2; pair++) {
                int ncol = wn * 32 + pair * 16 + b_chk;
                unsigned bhh = (unsigned)__cvta_generic_to_shared(
                    &Bhi[buf][b_row][ncol]);
                unsigned bll = (unsigned)__cvta_generic_to_shared(
                    &Blo[buf][b_row][ncol]);
                ldsm_x4_t(bh[2 * pair][0], bh[2 * pair][1],
                          bh[2 * pair + 1][0], bh[2 * pair + 1][1], bhh);
                ldsm_x4_t(bl[2 * pair][0], bl[2 * pair][1],
                          bl[2 * pair + 1][0], bl[2 * pair + 1][1], bll);
            }
#pragma unroll
            for (int im = 0; im < 2; im++)
#pragma unroll
                for (int in = 0; in < 4; in++) {
                    MMA_BF16(c[im][in], al[im][0], al[im][1], al[im][2],
                             al[im][3], bh[in][0], bh[in][1]);
                    MMA_BF16(c[im][in], ah[im][0], ah[im][1], ah[im][2],
                             ah[im][3], bl[in][0], bl[in][1]);
                    MMA_BF16(c[im][in], ah[im][0], ah[im][1], ah[im][2],
                             ah[im][3], bh[in][0], bh[in][1]);
                }
        }

        if (kt < NKT - 1) stage(buf ^ 1);
        __syncthreads();
    }

    // ---- epilogue: write g_hwh (fp16, half2 stores) ----
#pragma unroll
    for (int in = 0; in < 4; in++) {
        int ncol = n0 + wn * 32 + in * 8 + 2 * tg;
        if (ncol >= DIM) continue;
#pragma unroll
        for (int im = 0; im < 2; im++) {
            int r0 = m0 + wm * 32 + im * 16 + g;
            if (r0 < N_NODES)
                *(__half2*)&g_hwh[r0 * DIM + ncol] =
                    __floats2half2_rn(c[im][in][0], c[im][in][1]);
            int r1 = r0 + 8;
            if (r1 < N_NODES)
                *(__half2*)&g_hwh[r1 * DIM + ncol] =
                    __floats2half2_rn(c[im][in][2], c[im][in][3]);
        }
    }
}

// ---------------- CSR aggregation (fp16 gather, half2 lanes) ------------------
__global__ __launch_bounds__(160)
void agg_kernel(const float* __restrict__ bl,
                const float* __restrict__ e1,
                const float* __restrict__ e2,
                int l) {
    __shared__ int s_pk[160];
    const int n = blockIdx.x;
    const int tid = threadIdx.x;
    const int start = g_start[n], end = g_start[n + 1];
    const float selfE = e1[l * 5 + 4] + e2[l * 3 + 0];
    float ax = 0.f, ay = 0.f;
    for (int base = start; base < end; base += 160) {
        int idx = base + tid;
        if (idx < end) s_pk[tid] = g_csr[idx];
        __syncthreads();
        int cnt = min(160, end - base);
        if (tid < 150) {
#pragma unroll 4
            for (int i = 0; i < cnt; i++) {
                int row = s_pk[i] & 0xFFFF;
                float2 f = __half22float2(
                    *(const __half2*)&g_hwh[row * DIM + 2 * tid]);
                ax += f.x; ay += f.y;
            }
        }
        __syncthreads();
    }
    if (tid < 150) {
        float em = g_emsum[l * N_NODES + n] + selfE;
        float2 s = __half22float2(*(const __half2*)&g_hwh[n * DIM + 2 * tid]);
        float2 o;
        o.x = ax + s.x + bl[2 * tid] + em;
        o.y = ay + s.y + bl[2 * tid + 1] + em;
        *(float2*)&g_agg[n * DIM + 2 * tid] = o;
    }
}

// ---------------- batch norm stats + coefficients ----------------------------
#define STAT_ROWS 50
__global__ void stats_kernel(int l) {
    int tid = threadIdx.x;            // 128
    int r0 = blockIdx.x * STAT_ROWS;
    float* st = &g_stats[l * 2 * DIM];
    int c0 = tid, c1 = tid + 128, c2 = tid + 256;
    float s0 = 0, q0 = 0, s1 = 0, q1 = 0, s2 = 0, q2 = 0;
    int rend = r0 + STAT_ROWS;
    if (rend > N_NODES) rend = N_NODES;
#pragma unroll 4
    for (int r = r0; r < rend; r++) {
        const float* p = &g_agg[(long)r * DIM];
        float v0 = p[c0]; s0 += v0; q0 += v0 * v0;
        float v1 = p[c1]; s1 += v1; q1 += v1 * v1;
        if (c2 < DIM) { float v2 = p[c2]; s2 += v2; q2 += v2 * v2; }
    }
    atomicAdd(&st[c0], s0);
    atomicAdd(&st[DIM + c0], q0);
    atomicAdd(&st[c1], s1);
    atomicAdd(&st[DIM + c1], q1);
    if (c2 < DIM) {
        atomicAdd(&st[c2], s2);
        atomicAdd(&st[DIM + c2], q2);
    }
}

__global__ void coef_kernel(const float* __restrict__ gamma,
                            const float* __restrict__ beta, int l) {
    int d = blockIdx.x * blockDim.x + threadIdx.x;
    if (d >= DIM) return;
    const float* st = &g_stats[l * 2 * DIM];
    const float inv_n = 1.0f / (float)N_NODES;
    float mu = st[d] * inv_n;
    float var = st[DIM + d] * inv_n - mu * mu;
    float s = rsqrtf(var + EPS) * gamma[l * DIM + d];
    g_coef[d] = s;
    g_coef[DIM + d] = beta[l * DIM + d] - mu * s;
}

// ---------------- pool (applies final BN; batch sorted -> segments) ----------
__global__ void gbound_kernel(const int* __restrict__ batch) {
    int g = blockIdx.x * blockDim.x + threadIdx.x;
    if (g > N_GRAPHS) return;
    int lo = 0, hi = N_NODES;
    while (lo < hi) {
        int mid = (lo + hi) >> 1;
        if (batch[mid] < g) lo = mid + 1; else hi = mid;
    }
    g_gstart[g] = lo;
}

__global__ __launch_bounds__(128)
void pool_kernel() {
    const int g = blockIdx.x;
    const int tid = threadIdx.x;
    const int gs = g_gstart[g], ge = g_gstart[g + 1];
    const int d0 = tid, d1 = tid + 128, d2 = tid + 256;
    float a0 = 0.f, a1 = 0.f, a2 = 0.f;
#pragma unroll 2
    for (int r = gs; r < ge; r++) {
        const float* p = g_agg + r * DIM;
        a0 += p[d0];
        a1 += p[d1];
        if (d2 < DIM) a2 += p[d2];
    }
    float inv = 1.0f / fmaxf((float)(ge - gs), 1.0f);
    float* op = g_hg + g * DIM;
    op[d0] = (a0 * inv) * g_coef[d0] + g_coef[DIM + d0];
    op[d1] = (a1 * inv) * g_coef[d1] + g_coef[DIM + d1];
    if (d2 < DIM) op[d2] = (a2 * inv) * g_coef[d2] + g_coef[DIM + d2];
}

// ---------------- head MLPs --------------------------------------------------
__global__ void gemm_feat(const float* __restrict__ fw,
                          const float* __restrict__ fb,
                          float* __restrict__ hfeat) {
    __shared__ float sh[DIM];
    int g = blockIdx.x;
    int t = threadIdx.x;  // 256
    for (int k = t; k < DIM; k += FEAT) sh[k] = g_hg[g * DIM + k];
    __syncthreads();
    float acc = fb[t];
    for (int k = 0; k < DIM; k++) acc += sh[k] * fw[k * FEAT + t];
    hfeat[g * FEAT + t] = acc;
}

__global__ void gemm_mlp1(const float* __restrict__ hfeat,
                          const float* __restrict__ w1,
                          const float* __restrict__ b1) {
    __shared__ float sh[FEAT];
    int g = blockIdx.x;
    int t = threadIdx.x;  // 256
    sh[t] = hfeat[g * FEAT + t];
    __syncthreads();
    float acc = b1[t];
    for (int k = 0; k < FEAT; k++) acc += sh[k] * w1[k * FEAT + t];
    g_hid[g * FEAT + t] = fmaxf(acc, 0.f);
}

__global__ void gemm_mlp2(const float* __restrict__ w2,
                          const float* __restrict__ b2,
                          float* __restrict__ out) {
    __shared__ float sh[FEAT];
    int g = blockIdx.x;
    int t = threadIdx.x;  // 128
    sh[t] = g_hid[g * FEAT + t];
    sh[t + 128] = g_hid[g * FEAT + t + 128];
    __syncthreads();
    float acc = b2[t];
    for (int k = 0; k < FEAT; k++) acc += sh[k] * w2[k * 128 + t];
    out[g * 128 + t] = acc;
}

// ---------------- launch -----------------------------------------------------
extern "C" void kernel_launch(void* const* d_in, const int* in_sizes, int n_in,
                              void* d_out, int out_size) {
    const int*   x     = (const int*)d_in[0];
    const int*   ei    = (const int*)d_in[1];
    const int*   ea    = (const int*)d_in[2];
    const int*   batch = (const int*)d_in[3];
    const float* emb1  = (const float*)d_in[4];
    const float* emb2  = (const float*)d_in[5];
    const float* W     = (const float*)d_in[6];
    const float* b     = (const float*)d_in[7];
    const float* e1    = (const float*)d_in[8];
    const float* e2    = (const float*)d_in[9];
    const float* gamma = (const float*)d_in[10];
    const float* beta  = (const float*)d_in[11];
    const float* fw    = (const float*)d_in[12];
    const float* fb    = (const float*)d_in[13];
    const float* w1    = (const float*)d_in[14];
    const float* b1    = (const float*)d_in[15];
    const float* w2    = (const float*)d_in[16];
    const float* b2    = (const float*)d_in[17];

    float* hfeat_out = (float*)d_out;
    float* final_out = (float*)d_out + N_GRAPHS * FEAT;

    float* d_h;   cudaGetSymbolAddress((void**)&d_h, g_h);
    float* d_agg; cudaGetSymbolAddress((void**)&d_agg, g_agg);

    dim3 ggrid((DIM + 63) / 64, (N_NODES + 127) / 128);

    // Launch order puts gemm_layer_tc at position #4 for ncu attribution.
    embed_kernel<<<(N_NODES * DIM + 255) / 256, 256>>>(x, emb1, emb2);  // 1
    hist_kernel<<<(N_EDGES + 255) / 256, 256>>>(ei);                    // 2
    scan1_kernel<<<NBLK_SCAN, 256>>>();                                 // 3
    gemm_layer_tc<<<ggrid, 256>>>(W, d_h, 0);                           // 4 (l=0)
    scan2_kernel<<<1, 256>>>();                                         // 5
    scan3_kernel<<<(N_NODES + 255) / 256, 256>>>();                     // 6
    fill_kernel<<<(N_EDGES + 255) / 256, 256>>>(ei, ea);                // 7
    emsum_kernel<<<NBLK_SCAN, 256>>>(e1, e2);                           // 8

    for (int l = 0; l < N_LAYERS; l++) {
        if (l > 0)
            gemm_layer_tc<<<ggrid, 256>>>(W + (long)l * DIM * DIM, d_agg, 1);
        agg_kernel<<<N_NODES, 160>>>(b + l * DIM, e1, e2, l);
        stats_kernel<<<N_NODES / STAT_ROWS, 128>>>(l);
        coef_kernel<<<2, 256>>>(gamma, beta, l);
    }

    gbound_kernel<<<(N_GRAPHS + 256) / 256, 256>>>(batch);
    pool_kernel<<<N_GRAPHS, 128>>>();

    gemm_feat<<<N_GRAPHS, FEAT>>>(fw, fb, hfeat_out);
    gemm_mlp1<<<N_GRAPHS, FEAT>>>(hfeat_out, w1, b1);
    gemm_mlp2<<<N_GRAPHS, 128>>>(w2, b2, final_out);
}

// round 11
// speedup vs baseline: 1.6030x; 1.0443x over previous
#include <cuda_runtime.h>
#include <cuda_fp16.h>
#include <cuda_bf16.h>
#include <cstdint>

#define N_NODES 50000
#define N_EDGES 800000
#define N_GRAPHS 1024
#define DIM 300
#define N_LAYERS 5
#define FEAT 256
#define EPS 1e-5f
#define NBLK_SCAN ((N_NODES + 255) / 256)   // 196

// padded plane geometry (no predicates in GEMM staging)
#define AROWS 50048        // 391 * 128
#define ACOLS 304          // 19 * 16
#define WROWS 304
#define WCOLS 320

// ---------------- scratch (static device globals; no allocation) -------------
__device__ __align__(16) __nv_bfloat16 g_ahi[AROWS * ACOLS];  // 30.4 MB
__device__ __align__(16) __nv_bfloat16 g_alo[AROWS * ACOLS];
__device__ __align__(16) __nv_bfloat16 g_whi[N_LAYERS * WROWS * WCOLS];
__device__ __align__(16) __nv_bfloat16 g_wlo[N_LAYERS * WROWS * WCOLS];
__device__ __half g_hwh[N_NODES * DIM];   // h @ W[l] in fp16 (30 MB)
__device__ float  g_agg[N_NODES * DIM];   // pre-BN accumulation
__device__ float  g_stats[N_LAYERS * 2 * DIM];
__device__ float  g_coef[2 * DIM];        // current layer BN scale/shift
__device__ float  g_emsum[N_LAYERS * N_NODES];  // per-node edge-emb sums
__device__ float  g_hg[N_GRAPHS * DIM];
__device__ float  g_hid[N_GRAPHS * FEAT];
// CSR build
__device__ int g_deg[N_NODES];
__device__ int g_incl[N_NODES];
__device__ int g_bsum[NBLK_SCAN];
__device__ int g_boff[NBLK_SCAN];
__device__ int g_cursor[N_NODES];
__device__ int g_start[N_NODES + 1];
__device__ int g_csr[N_EDGES];           // row | (attr<<16)
__device__ int g_gstart[N_GRAPHS + 1];

__device__ __forceinline__ unsigned bfus(__nv_bfloat16 b) {
    return (unsigned)__bfloat16_as_ushort(b);
}

// ---------------- weight split: W -> bf16 hi/lo padded planes ----------------
__global__ void wconv_kernel(const float* __restrict__ W) {
    int i = blockIdx.x * blockDim.x + threadIdx.x;
    if (i >= N_LAYERS * WROWS * WCOLS) return;
    int l = i / (WROWS * WCOLS);
    int r = i - l * (WROWS * WCOLS);
    int k = r / WCOLS, n = r - k * WCOLS;
    float v = (k < DIM && n < DIM) ? W[(size_t)l * DIM * DIM + k * DIM + n] : 0.f;
    __nv_bfloat16 h = __float2bfloat16_rn(v);
    g_whi[i] = h;
    g_wlo[i] = __float2bfloat16_rn(v - __bfloat162float(h));
}

// ---------------- node embedding -> layer-0 A planes; zero deg/stats ---------
__global__ void embed_kernel(const int* __restrict__ x,
                             const float* __restrict__ emb1,
                             const float* __restrict__ emb2) {
    int i = blockIdx.x * blockDim.x + threadIdx.x;
    if (i < N_LAYERS * 2 * DIM) g_stats[i] = 0.f;
    if (i < N_NODES) g_deg[i] = 0;
    if (i >= AROWS * ACOLS) return;
    int n = i / ACOLS, d = i - n * ACOLS;
    float v = 0.f;
    if (n < N_NODES && d < DIM)
        v = emb1[x[2 * n] * DIM + d] + emb2[x[2 * n + 1] * DIM + d];
    __nv_bfloat16 h = __float2bfloat16_rn(v);
    g_ahi[i] = h;
    g_alo[i] = __float2bfloat16_rn(v - __bfloat162float(h));
}

// ---------------- per-layer BN+ReLU convert: g_agg -> A planes ---------------
__global__ void convert_kernel() {
    int i = blockIdx.x * blockDim.x + threadIdx.x;
    if (i >= AROWS * ACOLS) return;
    int n = i / ACOLS, d = i - n * ACOLS;
    float v = 0.f;
    if (n < N_NODES && d < DIM)
        v = fmaxf(g_agg[n * DIM + d] * g_coef[d] + g_coef[DIM + d], 0.f);
    __nv_bfloat16 h = __float2bfloat16_rn(v);
    g_ahi[i] = h;
    g_alo[i] = __float2bfloat16_rn(v - __bfloat162float(h));
}

// ---------------- CSR build ---------------------------------------------------
__global__ void hist_kernel(const int* __restrict__ ei) {
    int e = blockIdx.x * blockDim.x + threadIdx.x;
    if (e >= N_EDGES) return;
    atomicAdd(&g_deg[ei[N_EDGES + e]], 1);
}

__global__ void scan1_kernel() {
    __shared__ int s[256];
    int tid = threadIdx.x;
    int i = blockIdx.x * 256 + tid;
    int v = (i < N_NODES) ? g_deg[i] : 0;
    s[tid] = v;
    __syncthreads();
#pragma unroll
    for (int off = 1; off < 256; off <<= 1) {
        int t = (tid >= off) ? s[tid - off] : 0;
        __syncthreads();
        s[tid] += t;
        __syncthreads();
    }
    if (i < N_NODES) g_incl[i] = s[tid];
    if (tid == 255) g_bsum[blockIdx.x] = s[255];
}

__global__ void scan2_kernel() {
    __shared__ int s[256];
    int tid = threadIdx.x;
    s[tid] = (tid < NBLK_SCAN) ? g_bsum[tid] : 0;
    __syncthreads();
#pragma unroll
    for (int off = 1; off < 256; off <<= 1) {
        int t = (tid >= off) ? s[tid - off] : 0;
        __syncthreads();
        s[tid] += t;
        __syncthreads();
    }
    if (tid < NBLK_SCAN) g_boff[tid] = s[tid] - g_bsum[tid];
}

__global__ void scan3_kernel() {
    int i = blockIdx.x * blockDim.x + threadIdx.x;
    if (i >= N_NODES) return;
    g_start[i + 1] = g_incl[i] + g_boff[i >> 8];
    g_cursor[i] = 0;
    if (i == 0) g_start[0] = 0;
}

__global__ void fill_kernel(const int* __restrict__ ei,
                            const int* __restrict__ ea) {
    int e = blockIdx.x * blockDim.x + threadIdx.x;
    if (e >= N_EDGES) return;
    int row = ei[e];
    int col = ei[N_EDGES + e];
    int attr = ea[2 * e] * 3 + ea[2 * e + 1];  // 0..8
    int pos = g_start[col] + atomicAdd(&g_cursor[col], 1);
    g_csr[pos] = row | (attr << 16);
}

// per-node sum of scalar edge embeddings, all layers at once
__global__ void emsum_kernel(const float* __restrict__ e1,
                             const float* __restrict__ e2) {
    __shared__ float tab[N_LAYERS][9];
    int tid = threadIdx.x;
    if (tid < N_LAYERS * 9) {
        int l = tid / 9, a = tid % 9;
        tab[l][a] = e1[l * 5 + a / 3] + e2[l * 3 + a % 3];
    }
    __syncthreads();
    int n = blockIdx.x * blockDim.x + tid;
    if (n >= N_NODES) return;
    float s[N_LAYERS] = {0.f, 0.f, 0.f, 0.f, 0.f};
    int e0 = g_start[n], e1i = g_start[n + 1];
    for (int e = e0; e < e1i; e++) {
        int a = g_csr[e] >> 16;
#pragma unroll
        for (int l = 0; l < N_LAYERS; l++) s[l] += tab[l][a];
    }
#pragma unroll
    for (int l = 0; l < N_LAYERS; l++) g_emsum[l * N_NODES + n] = s[l];
}

// ---------------- 3xBF16 tensor-core GEMM (cp.async + ldmatrix + mma) --------
#define MMA_BF16(cc, A0, A1, A2, A3, B0, B1)                                   \
    asm volatile(                                                              \
        "mma.sync.aligned.m16n8k16.row.col.f32.bf16.bf16.f32 "                 \
        "{%0,%1,%2,%3},{%4,%5,%6,%7},{%8,%9},{%0,%1,%2,%3};"                   \
        : "+f"(cc[0]), "+f"(cc[1]), "+f"(cc[2]), "+f"(cc[3])                   \
        : "r"(A0), "r"(A1), "r"(A2), "r"(A3), "r"(B0), "r"(B1));

__device__ __forceinline__ void ldsm_x4(unsigned& r0, unsigned& r1,
                                        unsigned& r2, unsigned& r3,
                                        unsigned addr) {
    asm volatile("ldmatrix.sync.aligned.m8n8.x4.shared.b16 {%0,%1,%2,%3}, [%4];"
                 : "=r"(r0), "=r"(r1), "=r"(r2), "=r"(r3) : "r"(addr));
}
__device__ __forceinline__ void ldsm_x4_t(unsigned& r0, unsigned& r1,
                                          unsigned& r2, unsigned& r3,
                                          unsigned addr) {
    asm volatile(
        "ldmatrix.sync.aligned.m8n8.x4.trans.shared.b16 {%0,%1,%2,%3}, [%4];"
        : "=r"(r0), "=r"(r1), "=r"(r2), "=r"(r3) : "r"(addr));
}
__device__ __forceinline__ void cp16(void* dst_smem, const void* src) {
    unsigned d = (unsigned)__cvta_generic_to_shared(dst_smem);
    asm volatile("cp.async.cg.shared.global [%0], [%1], 16;"
                 :: "r"(d), "l"(src) : "memory");
}

#define NKT 19   // ceil(300/16)
#define A_RS 24  // A row stride in bf16 (48 B -> group 3m mod 8, conflict-free)
#define B_RS 72  // B row stride in bf16 (144 B -> group k mod 8, conflict-free)

__global__ __launch_bounds__(256)
void gemm_layer_tc(const __nv_bfloat16* __restrict__ Whi,
                   const __nv_bfloat16* __restrict__ Wlo) {
    __shared__ __align__(16) __nv_bfloat16 Ahi[2][128][A_RS], Alo[2][128][A_RS];
    __shared__ __align__(16) __nv_bfloat16 Bhi[2][16][B_RS],  Blo[2][16][B_RS];

    const int tid = threadIdx.x;
    const int lane = tid & 31;
    const int warp = tid >> 5;
    const int g = lane >> 2;      // 0..7
    const int tg = lane & 3;      // 0..3
    const int wm = warp >> 1;     // 0..3 (m)
    const int wn = warp & 1;      // 0..1 (n)
    const int m0 = blockIdx.y * 128;
    const int n0 = blockIdx.x * 64;

    float c[2][4][4];
#pragma unroll
    for (int im = 0; im < 2; im++)
#pragma unroll
        for (int in = 0; in < 4; in++)
#pragma unroll
            for (int j = 0; j < 4; j++) c[im][in][j] = 0.f;

    // A staging: row a_m = tid&127, k-half (8 bf16 = 16 B) = tid>>7
    const int a_m = tid & 127;
    const int a_kh = tid >> 7;
    const size_t a_goff = (size_t)(m0 + a_m) * ACOLS + a_kh * 8;
    // B staging: 128 chunks of 16 B per plane; tid<128 -> hi plane, else lo
    const int b_idx = tid & 127;
    const int b_k = b_idx >> 3;            // 0..15
    const int b_nc = (b_idx & 7) * 8;      // 0..56
    const bool b_is_hi = (tid < 128);
    const __nv_bfloat16* wsrc = b_is_hi ? Whi : Wlo;

    auto stage = [&](int kt, int buf) {
        cp16(&Ahi[buf][a_m][a_kh * 8], g_ahi + a_goff + kt * 16);
        cp16(&Alo[buf][a_m][a_kh * 8], g_alo + a_goff + kt * 16);
        __nv_bfloat16* bd = b_is_hi ? &Bhi[buf][b_k][b_nc] : &Blo[buf][b_k][b_nc];
        cp16(bd, wsrc + (size_t)(kt * 16 + b_k) * WCOLS + n0 + b_nc);
        asm volatile("cp.async.commit_group;" ::: "memory");
    };

    // ldmatrix per-thread source offsets
    const int a_row = (lane & 15);
    const int a_chk = (lane >> 4) * 8;
    const int b_row = ((lane >> 3) & 1) * 8 + (lane & 7);
    const int b_chk = (lane >> 4) * 8;

    stage(0, 0);

#pragma unroll 1
    for (int kt = 0; kt < NKT; kt++) {
        const int buf = kt & 1;
        if (kt < NKT - 1) {
            stage(kt + 1, buf ^ 1);
            asm volatile("cp.async.wait_group 1;" ::: "memory");
        } else {
            asm volatile("cp.async.wait_group 0;" ::: "memory");
        }
        __syncthreads();

        {
            unsigned ah[2][4], al[2][4];
#pragma unroll
            for (int im = 0; im < 2; im++) {
                int mrow = wm * 32 + im * 16 + a_row;
                unsigned ahh = (unsigned)__cvta_generic_to_shared(
                    &Ahi[buf][mrow][a_chk]);
                unsigned all_ = (unsigned)__cvta_generic_to_shared(
                    &Alo[buf][mrow][a_chk]);
                ldsm_x4(ah[im][0], ah[im][1], ah[im][2], ah[im][3], ahh);
                ldsm_x4(al[im][0], al[im][1], al[im][2], al[im][3], all_);
            }
            unsigned bh[4][2], bl[4][2];
#pragma unroll
            for (int pair = 0; pair < 2; pair++) {
                int ncol = wn * 32 + pair * 16 + b_chk;
                unsigned bhh = (unsigned)__cvta_generic_to_shared(
                    &Bhi[buf][b_row][ncol]);
                unsigned bll = (unsigned)__cvta_generic_to_shared(
                    &Blo[buf][b_row][ncol]);
                ldsm_x4_t(bh[2 * pair][0], bh[2 * pair][1],
                          bh[2 * pair + 1][0], bh[2 * pair + 1][1], bhh);
                ldsm_x4_t(bl[2 * pair][0], bl[2 * pair][1],
                          bl[2 * pair + 1][0], bl[2 * pair + 1][1], bll);
            }
#pragma unroll
            for (int im = 0; im < 2; im++)
#pragma unroll
                for (int in = 0; in < 4; in++) {
                    MMA_BF16(c[im][in], al[im][0], al[im][1], al[im][2],
                             al[im][3], bh[in][0], bh[in][1]);
                    MMA_BF16(c[im][in], ah[im][0], ah[im][1], ah[im][2],
                             ah[im][3], bl[in][0], bl[in][1]);
                    MMA_BF16(c[im][in], ah[im][0], ah[im][1], ah[im][2],
                             ah[im][3], bh[in][0], bh[in][1]);
                }
        }
        __syncthreads();
    }

    // ---- epilogue: write g_hwh (fp16, half2 stores) ----
#pragma unroll
    for (int in = 0; in < 4; in++) {
        int ncol = n0 + wn * 32 + in * 8 + 2 * tg;
        if (ncol >= DIM) continue;
#pragma unroll
        for (int im = 0; im < 2; im++) {
            int r0 = m0 + wm * 32 + im * 16 + g;
            if (r0 < N_NODES)
                *(__half2*)&g_hwh[r0 * DIM + ncol] =
                    __floats2half2_rn(c[im][in][0], c[im][in][1]);
            int r1 = r0 + 8;
            if (r1 < N_NODES)
                *(__half2*)&g_hwh[r1 * DIM + ncol] =
                    __floats2half2_rn(c[im][in][2], c[im][in][3]);
        }
    }
}

// ---------------- CSR aggregation (fp16 gather, half2 lanes) ------------------
__global__ __launch_bounds__(160)
void agg_kernel(const float* __restrict__ bl,
                const float* __restrict__ e1,
                const float* __restrict__ e2,
                int l) {
    __shared__ int s_pk[160];
    const int n = blockIdx.x;
    const int tid = threadIdx.x;
    const int start = g_start[n], end = g_start[n + 1];
    const float selfE = e1[l * 5 + 4] + e2[l * 3 + 0];
    float ax = 0.f, ay = 0.f;
    for (int base = start; base < end; base += 160) {
        int idx = base + tid;
        if (idx < end) s_pk[tid] = g_csr[idx];
        __syncthreads();
        int cnt = min(160, end - base);
        if (tid < 150) {
#pragma unroll 4
            for (int i = 0; i < cnt; i++) {
                int row = s_pk[i] & 0xFFFF;
                float2 f = __half22float2(
                    *(const __half2*)&g_hwh[row * DIM + 2 * tid]);
                ax += f.x; ay += f.y;
            }
        }
        __syncthreads();
    }
    if (tid < 150) {
        float em = g_emsum[l * N_NODES + n] + selfE;
        float2 s = __half22float2(*(const __half2*)&g_hwh[n * DIM + 2 * tid]);
        float2 o;
        o.x = ax + s.x + bl[2 * tid] + em;
        o.y = ay + s.y + bl[2 * tid + 1] + em;
        *(float2*)&g_agg[n * DIM + 2 * tid] = o;
    }
}

// ---------------- batch norm stats + coefficients ----------------------------
#define STAT_ROWS 50
__global__ void stats_kernel(int l) {
    int tid = threadIdx.x;            // 128
    int r0 = blockIdx.x * STAT_ROWS;
    float* st = &g_stats[l * 2 * DIM];
    int c0 = tid, c1 = tid + 128, c2 = tid + 256;
    float s0 = 0, q0 = 0, s1 = 0, q1 = 0, s2 = 0, q2 = 0;
    int rend = r0 + STAT_ROWS;
    if (rend > N_NODES) rend = N_NODES;
#pragma unroll 4
    for (int r = r0; r < rend; r++) {
        const float* p = &g_agg[(long)r * DIM];
        float v0 = p[c0]; s0 += v0; q0 += v0 * v0;
        float v1 = p[c1]; s1 += v1; q1 += v1 * v1;
        if (c2 < DIM) { float v2 = p[c2]; s2 += v2; q2 += v2 * v2; }
    }
    atomicAdd(&st[c0], s0);
    atomicAdd(&st[DIM + c0], q0);
    atomicAdd(&st[c1], s1);
    atomicAdd(&st[DIM + c1], q1);
    if (c2 < DIM) {
        atomicAdd(&st[c2], s2);
        atomicAdd(&st[DIM + c2], q2);
    }
}

__global__ void coef_kernel(const float* __restrict__ gamma,
                            const float* __restrict__ beta, int l) {
    int d = blockIdx.x * blockDim.x + threadIdx.x;
    if (d >= DIM) return;
    const float* st = &g_stats[l * 2 * DIM];
    const float inv_n = 1.0f / (float)N_NODES;
    float mu = st[d] * inv_n;
    float var = st[DIM + d] * inv_n - mu * mu;
    float s = rsqrtf(var + EPS) * gamma[l * DIM + d];
    g_coef[d] = s;
    g_coef[DIM + d] = beta[l * DIM + d] - mu * s;
}

// ---------------- pool (applies final BN; batch sorted -> segments) ----------
__global__ void gbound_kernel(const int* __restrict__ batch) {
    int g = blockIdx.x * blockDim.x + threadIdx.x;
    if (g > N_GRAPHS) return;
    int lo = 0, hi = N_NODES;
    while (lo < hi) {
        int mid = (lo + hi) >> 1;
        if (batch[mid] < g) lo = mid + 1; else hi = mid;
    }
    g_gstart[g] = lo;
}

__global__ __launch_bounds__(128)
void pool_kernel() {
    const int g = blockIdx.x;
    const int tid = threadIdx.x;
    const int gs = g_gstart[g], ge = g_gstart[g + 1];
    const int d0 = tid, d1 = tid + 128, d2 = tid + 256;
    float a0 = 0.f, a1 = 0.f, a2 = 0.f;
#pragma unroll 2
    for (int r = gs; r < ge; r++) {
        const float* p = g_agg + r * DIM;
        a0 += p[d0];
        a1 += p[d1];
        if (d2 < DIM) a2 += p[d2];
    }
    float inv = 1.0f / fmaxf((float)(ge - gs), 1.0f);
    float* op = g_hg + g * DIM;
    op[d0] = (a0 * inv) * g_coef[d0] + g_coef[DIM + d0];
    op[d1] = (a1 * inv) * g_coef[d1] + g_coef[DIM + d1];
    if (d2 < DIM) op[d2] = (a2 * inv) * g_coef[d2] + g_coef[DIM + d2];
}

// ---------------- head MLPs --------------------------------------------------
__global__ void gemm_feat(const float* __restrict__ fw,
                          const float* __restrict__ fb,
                          float* __restrict__ hfeat) {
    __shared__ float sh[DIM];
    int g = blockIdx.x;
    int t = threadIdx.x;  // 256
    for (int k = t; k < DIM; k += FEAT) sh[k] = g_hg[g * DIM + k];
    __syncthreads();
    float acc = fb[t];
    for (int k = 0; k < DIM; k++) acc += sh[k] * fw[k * FEAT + t];
    hfeat[g * FEAT + t] = acc;
}

__global__ void gemm_mlp1(const float* __restrict__ hfeat,
                          const float* __restrict__ w1,
                          const float* __restrict__ b1) {
    __shared__ float sh[FEAT];
    int g = blockIdx.x;
    int t = threadIdx.x;  // 256
    sh[t] = hfeat[g * FEAT + t];
    __syncthreads();
    float acc = b1[t];
    for (int k = 0; k < FEAT; k++) acc += sh[k] * w1[k * FEAT + t];
    g_hid[g * FEAT + t] = fmaxf(acc, 0.f);
}

__global__ void gemm_mlp2(const float* __restrict__ w2,
                          const float* __restrict__ b2,
                          float* __restrict__ out) {
    __shared__ float sh[FEAT];
    int g = blockIdx.x;
    int t = threadIdx.x;  // 128
    sh[t] = g_hid[g * FEAT + t];
    sh[t + 128] = g_hid[g * FEAT + t + 128];
    __syncthreads();
    float acc = b2[t];
    for (int k = 0; k < FEAT; k++) acc += sh[k] * w2[k * 128 + t];
    out[g * 128 + t] = acc;
}

// ---------------- launch -----------------------------------------------------
extern "C" void kernel_launch(void* const* d_in, const int* in_sizes, int n_in,
                              void* d_out, int out_size) {
    const int*   x     = (const int*)d_in[0];
    const int*   ei    = (const int*)d_in[1];
    const int*   ea    = (const int*)d_in[2];
    const int*   batch = (const int*)d_in[3];
    const float* emb1  = (const float*)d_in[4];
    const float* emb2  = (const float*)d_in[5];
    const float* W     = (const float*)d_in[6];
    const float* b     = (const float*)d_in[7];
    const float* e1    = (const float*)d_in[8];
    const float* e2    = (const float*)d_in[9];
    const float* gamma = (const float*)d_in[10];
    const float* beta  = (const float*)d_in[11];
    const float* fw    = (const float*)d_in[12];
    const float* fb    = (const float*)d_in[13];
    const float* w1    = (const float*)d_in[14];
    const float* b1    = (const float*)d_in[15];
    const float* w2    = (const float*)d_in[16];
    const float* b2    = (const float*)d_in[17];

    float* hfeat_out = (float*)d_out;
    float* final_out = (float*)d_out + N_GRAPHS * FEAT;

    __nv_bfloat16 *d_whi, *d_wlo;
    cudaGetSymbolAddress((void**)&d_whi, g_whi);
    cudaGetSymbolAddress((void**)&d_wlo, g_wlo);

    dim3 ggrid((DIM + 63) / 64, (N_NODES + 127) / 128);  // 5 x 391
    const int plane_blocks = (AROWS * ACOLS + 255) / 256;

    // Launch order keeps gemm_layer_tc(l=0) at position #4 for ncu attribution.
    wconv_kernel<<<(N_LAYERS * WROWS * WCOLS + 255) / 256, 256>>>(W);   // 1
    embed_kernel<<<plane_blocks, 256>>>(x, emb1, emb2);                 // 2
    hist_kernel<<<(N_EDGES + 255) / 256, 256>>>(ei);                    // 3
    gemm_layer_tc<<<ggrid, 256>>>(d_whi, d_wlo);                        // 4 (l=0)
    scan1_kernel<<<NBLK_SCAN, 256>>>();                                 // 5
    scan2_kernel<<<1, 256>>>();                                         // 6
    scan3_kernel<<<(N_NODES + 255) / 256, 256>>>();                     // 7
    fill_kernel<<<(N_EDGES + 255) / 256, 256>>>(ei, ea);                // 8
    emsum_kernel<<<NBLK_SCAN, 256>>>(e1, e2);                           // 9

    for (int l = 0; l < N_LAYERS; l++) {
        if (l > 0)
            gemm_layer_tc<<<ggrid, 256>>>(d_whi + (size_t)l * WROWS * WCOLS,
                                          d_wlo + (size_t)l * WROWS * WCOLS);
        agg_kernel<<<N_NODES, 160>>>(b + l * DIM, e1, e2, l);
        stats_kernel<<<N_NODES / STAT_ROWS, 128>>>(l);
        coef_kernel<<<2, 256>>>(gamma, beta, l);
        if (l < N_LAYERS - 1)
            convert_kernel<<<plane_blocks, 256>>>();
    }

    gbound_kernel<<<(N_GRAPHS + 256) / 256, 256>>>(batch);
    pool_kernel<<<N_GRAPHS, 128>>>();

    gemm_feat<<<N_GRAPHS, FEAT>>>(fw, fb, hfeat_out);
    gemm_mlp1<<<N_GRAPHS, FEAT>>>(hfeat_out, w1, b1);
    gemm_mlp2<<<N_GRAPHS, 128>>>(w2, b2, final_out);
}

// round 12
// speedup vs baseline: 1.6536x; 1.0316x over previous
#include <cuda_runtime.h>
#include <cuda_fp16.h>
#include <cuda_bf16.h>
#include <cstdint>

#define N_NODES 50000
#define N_EDGES 800000
#define N_GRAPHS 1024
#define DIM 300
#define N_LAYERS 5
#define FEAT 256
#define EPS 1e-5f
#define NBLK_SCAN ((N_NODES + 255) / 256)   // 196

// padded plane geometry (no predicates in GEMM staging)
#define AROWS 50048        // 391 * 128
#define ACOLS 304          // 19 * 16
#define WROWS 304
#define WCOLS 320

// ---------------- scratch (static device globals; no allocation) -------------
__device__ __align__(16) __nv_bfloat16 g_ahi[AROWS * ACOLS];  // 30.4 MB
__device__ __align__(16) __nv_bfloat16 g_alo[AROWS * ACOLS];
__device__ __align__(16) __nv_bfloat16 g_whi[N_LAYERS * WROWS * WCOLS];
__device__ __align__(16) __nv_bfloat16 g_wlo[N_LAYERS * WROWS * WCOLS];
__device__ __half g_hwh[N_NODES * DIM];   // h @ W[l] in fp16 (30 MB)
__device__ float  g_agg[N_NODES * DIM];   // pre-BN accumulation
__device__ float  g_stats[N_LAYERS * 2 * DIM];
__device__ float  g_coef[2 * DIM];        // current layer BN scale/shift
__device__ float  g_emsum[N_LAYERS * N_NODES];  // per-node edge-emb sums
__device__ float  g_hg[N_GRAPHS * DIM];
__device__ float  g_hid[N_GRAPHS * FEAT];
// CSR build
__device__ int g_deg[N_NODES];
__device__ int g_incl[N_NODES];
__device__ int g_bsum[NBLK_SCAN];
__device__ int g_boff[NBLK_SCAN];
__device__ int g_cursor[N_NODES];
__device__ int g_start[N_NODES + 1];
__device__ int g_csr[N_EDGES];           // row | (attr<<16)
__device__ int g_gstart[N_GRAPHS + 1];

// ---------------- weight split: W -> bf16 hi/lo padded planes ----------------
__global__ void wconv_kernel(const float* __restrict__ W) {
    int i = blockIdx.x * blockDim.x + threadIdx.x;
    if (i >= N_LAYERS * WROWS * WCOLS) return;
    int l = i / (WROWS * WCOLS);
    int r = i - l * (WROWS * WCOLS);
    int k = r / WCOLS, n = r - k * WCOLS;
    float v = (k < DIM && n < DIM) ? W[(size_t)l * DIM * DIM + k * DIM + n] : 0.f;
    __nv_bfloat16 h = __float2bfloat16_rn(v);
    g_whi[i] = h;
    g_wlo[i] = __float2bfloat16_rn(v - __bfloat162float(h));
}

// ---------------- node embedding -> layer-0 A planes; zero deg/stats ---------
__global__ void embed_kernel(const int* __restrict__ x,
                             const float* __restrict__ emb1,
                             const float* __restrict__ emb2) {
    int i = blockIdx.x * blockDim.x + threadIdx.x;
    if (i < N_LAYERS * 2 * DIM) g_stats[i] = 0.f;
    if (i < N_NODES) g_deg[i] = 0;
    if (i >= AROWS * ACOLS) return;
    int n = i / ACOLS, d = i - n * ACOLS;
    float v = 0.f;
    if (n < N_NODES && d < DIM)
        v = emb1[x[2 * n] * DIM + d] + emb2[x[2 * n + 1] * DIM + d];
    __nv_bfloat16 h = __float2bfloat16_rn(v);
    g_ahi[i] = h;
    g_alo[i] = __float2bfloat16_rn(v - __bfloat162float(h));
}

// ---------------- per-layer BN+ReLU convert: g_agg -> A planes ---------------
__global__ void convert_kernel() {
    int i = blockIdx.x * blockDim.x + threadIdx.x;
    if (i >= AROWS * ACOLS) return;
    int n = i / ACOLS, d = i - n * ACOLS;
    float v = 0.f;
    if (n < N_NODES && d < DIM)
        v = fmaxf(g_agg[n * DIM + d] * g_coef[d] + g_coef[DIM + d], 0.f);
    __nv_bfloat16 h = __float2bfloat16_rn(v);
    g_ahi[i] = h;
    g_alo[i] = __float2bfloat16_rn(v - __bfloat162float(h));
}

// ---------------- CSR build ---------------------------------------------------
__global__ void hist_kernel(const int* __restrict__ ei) {
    int e = blockIdx.x * blockDim.x + threadIdx.x;
    if (e >= N_EDGES) return;
    atomicAdd(&g_deg[ei[N_EDGES + e]], 1);
}

__global__ void scan1_kernel() {
    __shared__ int s[256];
    int tid = threadIdx.x;
    int i = blockIdx.x * 256 + tid;
    int v = (i < N_NODES) ? g_deg[i] : 0;
    s[tid] = v;
    __syncthreads();
#pragma unroll
    for (int off = 1; off < 256; off <<= 1) {
        int t = (tid >= off) ? s[tid - off] : 0;
        __syncthreads();
        s[tid] += t;
        __syncthreads();
    }
    if (i < N_NODES) g_incl[i] = s[tid];
    if (tid == 255) g_bsum[blockIdx.x] = s[255];
}

__global__ void scan2_kernel() {
    __shared__ int s[256];
    int tid = threadIdx.x;
    s[tid] = (tid < NBLK_SCAN) ? g_bsum[tid] : 0;
    __syncthreads();
#pragma unroll
    for (int off = 1; off < 256; off <<= 1) {
        int t = (tid >= off) ? s[tid - off] : 0;
        __syncthreads();
        s[tid] += t;
        __syncthreads();
    }
    if (tid < NBLK_SCAN) g_boff[tid] = s[tid] - g_bsum[tid];
}

__global__ void scan3_kernel() {
    int i = blockIdx.x * blockDim.x + threadIdx.x;
    if (i >= N_NODES) return;
    g_start[i + 1] = g_incl[i] + g_boff[i >> 8];
    g_cursor[i] = 0;
    if (i == 0) g_start[0] = 0;
}

__global__ void fill_kernel(const int* __restrict__ ei,
                            const int* __restrict__ ea) {
    int e = blockIdx.x * blockDim.x + threadIdx.x;
    if (e >= N_EDGES) return;
    int row = ei[e];
    int col = ei[N_EDGES + e];
    int attr = ea[2 * e] * 3 + ea[2 * e + 1];  // 0..8
    int pos = g_start[col] + atomicAdd(&g_cursor[col], 1);
    g_csr[pos] = row | (attr << 16);
}

// per-node sum of scalar edge embeddings, all layers at once
__global__ void emsum_kernel(const float* __restrict__ e1,
                             const float* __restrict__ e2) {
    __shared__ float tab[N_LAYERS][9];
    int tid = threadIdx.x;
    if (tid < N_LAYERS * 9) {
        int l = tid / 9, a = tid % 9;
        tab[l][a] = e1[l * 5 + a / 3] + e2[l * 3 + a % 3];
    }
    __syncthreads();
    int n = blockIdx.x * blockDim.x + tid;
    if (n >= N_NODES) return;
    float s[N_LAYERS] = {0.f, 0.f, 0.f, 0.f, 0.f};
    int e0 = g_start[n], e1i = g_start[n + 1];
    for (int e = e0; e < e1i; e++) {
        int a = g_csr[e] >> 16;
#pragma unroll
        for (int l = 0; l < N_LAYERS; l++) s[l] += tab[l][a];
    }
#pragma unroll
    for (int l = 0; l < N_LAYERS; l++) g_emsum[l * N_NODES + n] = s[l];
}

// ---------------- 3xBF16 tensor-core GEMM (3-stage cp.async + ldmatrix) ------
#define MMA_BF16(cc, A0, A1, A2, A3, B0, B1)                                   \
    asm volatile(                                                              \
        "mma.sync.aligned.m16n8k16.row.col.f32.bf16.bf16.f32 "                 \
        "{%0,%1,%2,%3},{%4,%5,%6,%7},{%8,%9},{%0,%1,%2,%3};"                   \
        : "+f"(cc[0]), "+f"(cc[1]), "+f"(cc[2]), "+f"(cc[3])                   \
        : "r"(A0), "r"(A1), "r"(A2), "r"(A3), "r"(B0), "r"(B1));

__device__ __forceinline__ void ldsm_x4(unsigned& r0, unsigned& r1,
                                        unsigned& r2, unsigned& r3,
                                        unsigned addr) {
    asm volatile("ldmatrix.sync.aligned.m8n8.x4.shared.b16 {%0,%1,%2,%3}, [%4];"
                 : "=r"(r0), "=r"(r1), "=r"(r2), "=r"(r3) : "r"(addr));
}
__device__ __forceinline__ void ldsm_x4_t(unsigned& r0, unsigned& r1,
                                          unsigned& r2, unsigned& r3,
                                          unsigned addr) {
    asm volatile(
        "ldmatrix.sync.aligned.m8n8.x4.trans.shared.b16 {%0,%1,%2,%3}, [%4];"
        : "=r"(r0), "=r"(r1), "=r"(r2), "=r"(r3) : "r"(addr));
}
__device__ __forceinline__ void cp16(void* dst_smem, const void* src) {
    unsigned d = (unsigned)__cvta_generic_to_shared(dst_smem);
    asm volatile("cp.async.cg.shared.global [%0], [%1], 16;"
                 :: "r"(d), "l"(src) : "memory");
}

#define NKT 19   // ceil(300/16)
#define A_RS 24  // A row stride in bf16 (48 B -> group 3m mod 8, conflict-free)
#define B_RS 72  // B row stride in bf16 (144 B -> group k mod 8, conflict-free)
#define GSTAGES 3
#define A_PLANE (128 * A_RS)   // bf16 per stage per plane
#define B_PLANE (16 * B_RS)
#define GEMM_SMEM ((size_t)GSTAGES * (2 * A_PLANE + 2 * B_PLANE) * 2)  // 50688 B

__global__ __launch_bounds__(256)
void gemm_layer_tc(const __nv_bfloat16* __restrict__ Whi,
                   const __nv_bfloat16* __restrict__ Wlo) {
    extern __shared__ __align__(16) __nv_bfloat16 smp[];
    __nv_bfloat16* Ahi = smp;                          // [GSTAGES][128][A_RS]
    __nv_bfloat16* Alo = Ahi + GSTAGES * A_PLANE;
    __nv_bfloat16* Bhi = Alo + GSTAGES * A_PLANE;      // [GSTAGES][16][B_RS]
    __nv_bfloat16* Blo = Bhi + GSTAGES * B_PLANE;

    const int tid = threadIdx.x;
    const int lane = tid & 31;
    const int warp = tid >> 5;
    const int g = lane >> 2;      // 0..7
    const int tg = lane & 3;      // 0..3
    const int wm = warp >> 1;     // 0..3 (m)
    const int wn = warp & 1;      // 0..1 (n)
    const int m0 = blockIdx.y * 128;
    const int n0 = blockIdx.x * 64;

    float c[2][4][4];
#pragma unroll
    for (int im = 0; im < 2; im++)
#pragma unroll
        for (int in = 0; in < 4; in++)
#pragma unroll
            for (int j = 0; j < 4; j++) c[im][in][j] = 0.f;

    // A staging: row a_m = tid&127, k-half (8 bf16 = 16 B) = tid>>7
    const int a_m = tid & 127;
    const int a_kh = tid >> 7;
    const size_t a_goff = (size_t)(m0 + a_m) * ACOLS + a_kh * 8;
    // B staging: 128 chunks of 16 B per plane; tid<128 -> hi plane, else lo
    const int b_idx = tid & 127;
    const int b_k = b_idx >> 3;            // 0..15
    const int b_nc = (b_idx & 7) * 8;      // 0..56
    const bool b_is_hi = (tid < 128);
    const __nv_bfloat16* wsrc = b_is_hi ? Whi : Wlo;

    auto stage = [&](int kt) {
        int buf = kt % GSTAGES;
        cp16(Ahi + (buf * 128 + a_m) * A_RS + a_kh * 8,
             g_ahi + a_goff + kt * 16);
        cp16(Alo + (buf * 128 + a_m) * A_RS + a_kh * 8,
             g_alo + a_goff + kt * 16);
        __nv_bfloat16* bd = (b_is_hi ? Bhi : Blo) + (buf * 16 + b_k) * B_RS + b_nc;
        cp16(bd, wsrc + (size_t)(kt * 16 + b_k) * WCOLS + n0 + b_nc);
        asm volatile("cp.async.commit_group;" ::: "memory");
    };

    // ldmatrix per-thread source offsets
    const int a_row = (lane & 15);
    const int a_chk = (lane >> 4) * 8;
    const int b_row = ((lane >> 3) & 1) * 8 + (lane & 7);
    const int b_chk = (lane >> 4) * 8;

    stage(0);
    stage(1);

#pragma unroll 1
    for (int kt = 0; kt < NKT; kt++) {
        const int buf = kt % GSTAGES;
        if (kt < NKT - 1)
            asm volatile("cp.async.wait_group 1;" ::: "memory");
        else
            asm volatile("cp.async.wait_group 0;" ::: "memory");
        __syncthreads();

        {
            unsigned ah[2][4], al[2][4];
#pragma unroll
            for (int im = 0; im < 2; im++) {
                int mrow = buf * 128 + wm * 32 + im * 16 + a_row;
                unsigned ahh = (unsigned)__cvta_generic_to_shared(
                    Ahi + mrow * A_RS + a_chk);
                unsigned all_ = (unsigned)__cvta_generic_to_shared(
                    Alo + mrow * A_RS + a_chk);
                ldsm_x4(ah[im][0], ah[im][1], ah[im][2], ah[im][3], ahh);
                ldsm_x4(al[im][0], al[im][1], al[im][2], al[im][3], all_);
            }
            unsigned bh[4][2], bl[4][2];
#pragma unroll
            for (int pair = 0; pair < 2; pair++) {
                int ncol = wn * 32 + pair * 16 + b_chk;
                int brw = buf * 16 + b_row;
                unsigned bhh = (unsigned)__cvta_generic_to_shared(
                    Bhi + brw * B_RS + ncol);
                unsigned bll = (unsigned)__cvta_generic_to_shared(
                    Blo + brw * B_RS + ncol);
                ldsm_x4_t(bh[2 * pair][0], bh[2 * pair][1],
                          bh[2 * pair + 1][0], bh[2 * pair + 1][1], bhh);
                ldsm_x4_t(bl[2 * pair][0], bl[2 * pair][1],
                          bl[2 * pair + 1][0], bl[2 * pair + 1][1], bll);
            }
#pragma unroll
            for (int im = 0; im < 2; im++)
#pragma unroll
                for (int in = 0; in < 4; in++) {
                    MMA_BF16(c[im][in], al[im][0], al[im][1], al[im][2],
                             al[im][3], bh[in][0], bh[in][1]);
                    MMA_BF16(c[im][in], ah[im][0], ah[im][1], ah[im][2],
                             ah[im][3], bl[in][0], bl[in][1]);
                    MMA_BF16(c[im][in], ah[im][0], ah[im][1], ah[im][2],
                             ah[im][3], bh[in][0], bh[in][1]);
                }
        }

        // Stage kt+2 into buffer (kt+2)%3 = (kt-1)%3. All threads finished
        // reading that buffer (compute kt-1) before this iteration's barrier.
        if (kt + 2 < NKT) stage(kt + 2);
    }

    // ---- epilogue: write g_hwh (fp16, half2 stores) ----
#pragma unroll
    for (int in = 0; in < 4; in++) {
        int ncol = n0 + wn * 32 + in * 8 + 2 * tg;
        if (ncol >= DIM) continue;
#pragma unroll
        for (int im = 0; im < 2; im++) {
            int r0 = m0 + wm * 32 + im * 16 + g;
            if (r0 < N_NODES)
                *(__half2*)&g_hwh[r0 * DIM + ncol] =
                    __floats2half2_rn(c[im][in][0], c[im][in][1]);
            int r1 = r0 + 8;
            if (r1 < N_NODES)
                *(__half2*)&g_hwh[r1 * DIM + ncol] =
                    __floats2half2_rn(c[im][in][2], c[im][in][3]);
        }
    }
}

// ---------------- CSR aggregation (fp16 gather, half2 lanes) ------------------
__global__ __launch_bounds__(160)
void agg_kernel(const float* __restrict__ bl,
                const float* __restrict__ e1,
                const float* __restrict__ e2,
                int l) {
    __shared__ int s_pk[160];
    const int n = blockIdx.x;
    const int tid = threadIdx.x;
    const int start = g_start[n], end = g_start[n + 1];
    const float selfE = e1[l * 5 + 4] + e2[l * 3 + 0];
    float ax = 0.f, ay = 0.f;
    for (int base = start; base < end; base += 160) {
        int idx = base + tid;
        if (idx < end) s_pk[tid] = g_csr[idx];
        __syncthreads();
        int cnt = min(160, end - base);
        if (tid < 150) {
#pragma unroll 8
            for (int i = 0; i < cnt; i++) {
                int row = s_pk[i] & 0xFFFF;
                float2 f = __half22float2(
                    *(const __half2*)&g_hwh[row * DIM + 2 * tid]);
                ax += f.x; ay += f.y;
            }
        }
        __syncthreads();
    }
    if (tid < 150) {
        float em = g_emsum[l * N_NODES + n] + selfE;
        float2 s = __half22float2(*(const __half2*)&g_hwh[n * DIM + 2 * tid]);
        float2 o;
        o.x = ax + s.x + bl[2 * tid] + em;
        o.y = ay + s.y + bl[2 * tid + 1] + em;
        *(float2*)&g_agg[n * DIM + 2 * tid] = o;
    }
}

// ---------------- batch norm stats + coefficients ----------------------------
#define STAT_ROWS 50
__global__ void stats_kernel(int l) {
    int tid = threadIdx.x;            // 128
    int r0 = blockIdx.x * STAT_ROWS;
    float* st = &g_stats[l * 2 * DIM];
    int c0 = tid, c1 = tid + 128, c2 = tid + 256;
    float s0 = 0, q0 = 0, s1 = 0, q1 = 0, s2 = 0, q2 = 0;
    int rend = r0 + STAT_ROWS;
    if (rend > N_NODES) rend = N_NODES;
#pragma unroll 4
    for (int r = r0; r < rend; r++) {
        const float* p = &g_agg[(long)r * DIM];
        float v0 = p[c0]; s0 += v0; q0 += v0 * v0;
        float v1 = p[c1]; s1 += v1; q1 += v1 * v1;
        if (c2 < DIM) { float v2 = p[c2]; s2 += v2; q2 += v2 * v2; }
    }
    atomicAdd(&st[c0], s0);
    atomicAdd(&st[DIM + c0], q0);
    atomicAdd(&st[c1], s1);
    atomicAdd(&st[DIM + c1], q1);
    if (c2 < DIM) {
        atomicAdd(&st[c2], s2);
        atomicAdd(&st[DIM + c2], q2);
    }
}

__global__ void coef_kernel(const float* __restrict__ gamma,
                            const float* __restrict__ beta, int l) {
    int d = blockIdx.x * blockDim.x + threadIdx.x;
    if (d >= DIM) return;
    const float* st = &g_stats[l * 2 * DIM];
    const float inv_n = 1.0f / (float)N_NODES;
    float mu = st[d] * inv_n;
    float var = st[DIM + d] * inv_n - mu * mu;
    float s = rsqrtf(var + EPS) * gamma[l * DIM + d];
    g_coef[d] = s;
    g_coef[DIM + d] = beta[l * DIM + d] - mu * s;
}

// ---------------- pool (applies final BN; batch sorted -> segments) ----------
__global__ void gbound_kernel(const int* __restrict__ batch) {
    int g = blockIdx.x * blockDim.x + threadIdx.x;
    if (g > N_GRAPHS) return;
    int lo = 0, hi = N_NODES;
    while (lo < hi) {
        int mid = (lo + hi) >> 1;
        if (batch[mid] < g) lo = mid + 1; else hi = mid;
    }
    g_gstart[g] = lo;
}

__global__ __launch_bounds__(128)
void pool_kernel() {
    const int g = blockIdx.x;
    const int tid = threadIdx.x;
    const int gs = g_gstart[g], ge = g_gstart[g + 1];
    const int d0 = tid, d1 = tid + 128, d2 = tid + 256;
    float a0 = 0.f, a1 = 0.f, a2 = 0.f;
#pragma unroll 2
    for (int r = gs; r < ge; r++) {
        const float* p = g_agg + r * DIM;
        a0 += p[d0];
        a1 += p[d1];
        if (d2 < DIM) a2 += p[d2];
    }
    float inv = 1.0f / fmaxf((float)(ge - gs), 1.0f);
    float* op = g_hg + g * DIM;
    op[d0] = (a0 * inv) * g_coef[d0] + g_coef[DIM + d0];
    op[d1] = (a1 * inv) * g_coef[d1] + g_coef[DIM + d1];
    if (d2 < DIM) op[d2] = (a2 * inv) * g_coef[d2] + g_coef[DIM + d2];
}

// ---------------- head MLPs --------------------------------------------------
__global__ void gemm_feat(const float* __restrict__ fw,
                          const float* __restrict__ fb,
                          float* __restrict__ hfeat) {
    __shared__ float sh[DIM];
    int g = blockIdx.x;
    int t = threadIdx.x;  // 256
    for (int k = t; k < DIM; k += FEAT) sh[k] = g_hg[g * DIM + k];
    __syncthreads();
    float acc = fb[t];
    for (int k = 0; k < DIM; k++) acc += sh[k] * fw[k * FEAT + t];
    hfeat[g * FEAT + t] = acc;
}

__global__ void gemm_mlp1(const float* __restrict__ hfeat,
                          const float* __restrict__ w1,
                          const float* __restrict__ b1) {
    __shared__ float sh[FEAT];
    int g = blockIdx.x;
    int t = threadIdx.x;  // 256
    sh[t] = hfeat[g * FEAT + t];
    __syncthreads();
    float acc = b1[t];
    for (int k = 0; k < FEAT; k++) acc += sh[k] * w1[k * FEAT + t];
    g_hid[g * FEAT + t] = fmaxf(acc, 0.f);
}

__global__ void gemm_mlp2(const float* __restrict__ w2,
                          const float* __restrict__ b2,
                          float* __restrict__ out) {
    __shared__ float sh[FEAT];
    int g = blockIdx.x;
    int t = threadIdx.x;  // 128
    sh[t] = g_hid[g * FEAT + t];
    sh[t + 128] = g_hid[g * FEAT + t + 128];
    __syncthreads();
    float acc = b2[t];
    for (int k = 0; k < FEAT; k++) acc += sh[k] * w2[k * 128 + t];
    out[g * 128 + t] = acc;
}

// ---------------- launch -----------------------------------------------------
extern "C" void kernel_launch(void* const* d_in, const int* in_sizes, int n_in,
                              void* d_out, int out_size) {
    const int*   x     = (const int*)d_in[0];
    const int*   ei    = (const int*)d_in[1];
    const int*   ea    = (const int*)d_in[2];
    const int*   batch = (const int*)d_in[3];
    const float* emb1  = (const float*)d_in[4];
    const float* emb2  = (const float*)d_in[5];
    const float* W     = (const float*)d_in[6];
    const float* b     = (const float*)d_in[7];
    const float* e1    = (const float*)d_in[8];
    const float* e2    = (const float*)d_in[9];
    const float* gamma = (const float*)d_in[10];
    const float* beta  = (const float*)d_in[11];
    const float* fw    = (const float*)d_in[12];
    const float* fb    = (const float*)d_in[13];
    const float* w1    = (const float*)d_in[14];
    const float* b1    = (const float*)d_in[15];
    const float* w2    = (const float*)d_in[16];
    const float* b2    = (const float*)d_in[17];

    float* hfeat_out = (float*)d_out;
    float* final_out = (float*)d_out + N_GRAPHS * FEAT;

    __nv_bfloat16 *d_whi, *d_wlo;
    cudaGetSymbolAddress((void**)&d_whi, g_whi);
    cudaGetSymbolAddress((void**)&d_wlo, g_wlo);

    cudaFuncSetAttribute(gemm_layer_tc,
                         cudaFuncAttributeMaxDynamicSharedMemorySize,
                         (int)GEMM_SMEM);

    dim3 ggrid((DIM + 63) / 64, (N_NODES + 127) / 128);  // 5 x 391
    const int plane_blocks = (AROWS * ACOLS + 255) / 256;

    // Launch order keeps gemm_layer_tc(l=0) at position #4 for ncu attribution.
    wconv_kernel<<<(N_LAYERS * WROWS * WCOLS + 255) / 256, 256>>>(W);   // 1
    embed_kernel<<<plane_blocks, 256>>>(x, emb1, emb2);                 // 2
    hist_kernel<<<(N_EDGES + 255) / 256, 256>>>(ei);                    // 3
    gemm_layer_tc<<<ggrid, 256, GEMM_SMEM>>>(d_whi, d_wlo);             // 4 (l=0)
    scan1_kernel<<<NBLK_SCAN, 256>>>();                                 // 5
    scan2_kernel<<<1, 256>>>();                                         // 6
    scan3_kernel<<<(N_NODES + 255) / 256, 256>>>();                     // 7
    fill_kernel<<<(N_EDGES + 255) / 256, 256>>>(ei, ea);                // 8
    emsum_kernel<<<NBLK_SCAN, 256>>>(e1, e2);                           // 9

    for (int l = 0; l < N_LAYERS; l++) {
        if (l > 0)
            gemm_layer_tc<<<ggrid, 256, GEMM_SMEM>>>(
                d_whi + (size_t)l * WROWS * WCOLS,
                d_wlo + (size_t)l * WROWS * WCOLS);
        agg_kernel<<<N_NODES, 160>>>(b + l * DIM, e1, e2, l);
        stats_kernel<<<N_NODES / STAT_ROWS, 128>>>(l);
        coef_kernel<<<2, 256>>>(gamma, beta, l);
        if (l < N_LAYERS - 1)
            convert_kernel<<<plane_blocks, 256>>>();
    }

    gbound_kernel<<<(N_GRAPHS + 256) / 256, 256>>>(batch);
    pool_kernel<<<N_GRAPHS, 128>>>();

    gemm_feat<<<N_GRAPHS, FEAT>>>(fw, fb, hfeat_out);
    gemm_mlp1<<<N_GRAPHS, FEAT>>>(hfeat_out, w1, b1);
    gemm_mlp2<<<N_GRAPHS, 128>>>(w2, b2, final_out);
}